// round 5
// baseline (speedup 1.0000x reference)
#include <cuda_runtime.h>
#include <math_constants.h>

#define NB 128
#define NT 512

// scratch
__device__ float g_conv1[64 * 16384];
__device__ float g_h[64 * 256];
__device__ float g_logits[64 * 1024];
__device__ float g_wpack[1141760];
__device__ unsigned g_bar;
__device__ volatile unsigned g_gen;

// packed-weight offsets (floats)
#define OFF_W1 0          // 16384 pos * 52
#define OFF_W2 851968     // 4096 * 32
#define OFF_W3 983040     // 4096 * 32
#define OFF_W4 1114112    // 1024 * 12
#define OFF_W5 1126400    // 1024 * 12
#define OFF_W6 1138688    // 256 * 12

// ---------------------------------------------------------------------------
// Grid-wide barrier (all NB blocks co-resident: NB=128 <= 148 SMs, 1 wave).
// ---------------------------------------------------------------------------
__device__ __forceinline__ void grid_sync(unsigned& gen) {
    __syncthreads();
    if (threadIdx.x == 0) {
        __threadfence();
        unsigned my = gen;
        if (atomicInc(&g_bar, NB - 1) == NB - 1) {
            g_gen = my + 1;                       // release (counter auto-wrapped)
        } else {
            while (g_gen == my) __nanosleep(64);  // volatile spin
        }
        gen = my + 1;
        __threadfence();
    }
    __syncthreads();
}

// block stats (sum, sumsq) over 512 threads = 16 warps; deterministic tree
__device__ __forceinline__ float2 bstats(float s, float ss) {
    __shared__ float r0[16], r1[16];
    int tid = threadIdx.x, wid = tid >> 5, lid = tid & 31;
#pragma unroll
    for (int o = 16; o; o >>= 1) {
        s += __shfl_down_sync(0xFFFFFFFFu, s, o);
        ss += __shfl_down_sync(0xFFFFFFFFu, ss, o);
    }
    if (lid == 0) { r0[wid] = s; r1[wid] = ss; }
    __syncthreads();
    if (wid == 0 && lid < 16) {
        s = r0[lid];
        ss = r1[lid];
#pragma unroll
        for (int o = 8; o; o >>= 1) {
            s += __shfl_down_sync(0x0000FFFFu, s, o);
            ss += __shfl_down_sync(0x0000FFFFu, ss, o);
        }
        if (lid == 0) { r0[0] = s; r1[0] = ss; }
    }
    __syncthreads();
    float2 res = make_float2(r0[0], r1[0]);
    __syncthreads();
    return res;
}

// ---------------------------------------------------------------------------
// THE kernel: pack -> conv1 -> per-sample net -> fc -> softmax, one launch.
// ---------------------------------------------------------------------------
__global__ void __launch_bounds__(NT) allnet_kernel(
    const float* __restrict__ x,
    const float* __restrict__ w1, const float* __restrict__ b1, const float* __restrict__ g1, const float* __restrict__ be1,
    const float* __restrict__ w2, const float* __restrict__ b2, const float* __restrict__ g2, const float* __restrict__ be2,
    const float* __restrict__ w3, const float* __restrict__ b3, const float* __restrict__ g3, const float* __restrict__ be3,
    const float* __restrict__ w4, const float* __restrict__ b4, const float* __restrict__ g4, const float* __restrict__ be4,
    const float* __restrict__ w5, const float* __restrict__ b5, const float* __restrict__ g5, const float* __restrict__ be5,
    const float* __restrict__ w6, const float* __restrict__ b6, const float* __restrict__ g6, const float* __restrict__ be6,
    const float* __restrict__ fcw, const float* __restrict__ fcb,
    float* __restrict__ out) {

    __shared__ float s_raw[9248];   // 36.1 KB: union of all phase buffers
    const int tid = threadIdx.x;
    const int bid = blockIdx.x;
    unsigned gen = 0;
    if (tid == 0) gen = g_gen;

    float* wp = g_wpack;

    // ===== Phase 0: pack weights (float4-aligned per-position strides) =====
    {
        int t = bid * NT + tid;
        const int nt = NB * NT;
        for (int i = t; i < 16384 * 49; i += nt) { int p = i / 49, k = i - p * 49; wp[OFF_W1 + p * 52 + k] = w1[i]; }
        for (int i = t; i < 4096 * 25; i += nt)  { int p = i / 25, k = i - p * 25; wp[OFF_W2 + p * 32 + k] = w2[i]; }
        for (int i = t; i < 4096 * 25; i += nt)  { int p = i / 25, k = i - p * 25; wp[OFF_W3 + p * 32 + k] = w3[i]; }
        for (int i = t; i < 1024 * 9; i += nt)   { int p = i / 9,  k = i - p * 9;  wp[OFF_W4 + p * 12 + k] = w4[i]; }
        for (int i = t; i < 1024 * 9; i += nt)   { int p = i / 9,  k = i - p * 9;  wp[OFF_W5 + p * 12 + k] = w5[i]; }
        for (int i = t; i < 256 * 9; i += nt)    { int p = i / 9,  k = i - p * 9;  wp[OFF_W6 + p * 12 + k] = w6[i]; }
    }
    grid_sync(gen);

    // ===== Phase 1: conv1 (128x128, K=7, pad=3) + ReLU -> g_conv1 =====
    // 256 units = 32 tiles (16x32) x 8 batch-groups; 2 units per block.
#pragma unroll 1
    for (int uu = 0; uu < 2; ++uu) {
        const int unit = bid * 2 + uu;
        const int tile = unit >> 3, bg = unit & 7;
        const int ti0 = (tile >> 2) * 16, tj0 = (tile & 3) * 32;
        // load 8 batches x (16+6) x (32+6) zero-padded input tile
        for (int e = tid; e < 8 * 22 * 38; e += NT) {
            int bb = e / 836;
            int rem = e - bb * 836;
            int r = rem / 38, c = rem - r * 38;
            int gi = ti0 - 3 + r, gj = tj0 - 3 + c;
            float v = 0.0f;
            if ((unsigned)gi < 128u && (unsigned)gj < 128u)
                v = x[(bg * 8 + bb) * 16384 + gi * 128 + gj];
            s_raw[e] = v;
        }
        __syncthreads();

        const int ti = tid >> 5, tj = tid & 31;
        const int p = (ti0 + ti) * 128 + tj0 + tj;
        float4 wreg[13];
        const float4* wv = (const float4*)(wp + OFF_W1 + p * 52);
#pragma unroll
        for (int t = 0; t < 13; ++t) wreg[t] = wv[t];
        const float* wf = (const float*)wreg;
        const float bias = __ldg(b1 + p);

        float acc[8];
#pragma unroll
        for (int bb = 0; bb < 8; ++bb) acc[bb] = bias;
#pragma unroll
        for (int u = 0; u < 7; ++u)
#pragma unroll
            for (int v = 0; v < 7; ++v) {
                float wvv = wf[u * 7 + v];
                int base = (ti + u) * 38 + tj + v;
#pragma unroll
                for (int bb = 0; bb < 8; ++bb)
                    acc[bb] = fmaf(s_raw[bb * 836 + base], wvv, acc[bb]);
            }
#pragma unroll
        for (int bb = 0; bb < 8; ++bb)
            g_conv1[(bg * 8 + bb) * 16384 + p] = fmaxf(acc[bb], 0.0f);
        __syncthreads();
    }
    grid_sync(gen);

    // ===== Phase 2: per-sample net (blocks 0..63) =====
    if (bid < 64) {
        float* SA = s_raw;          // 4624 floats (68x68 padded)
        float* SB = s_raw + 4624;
        const int b = bid;
        const float* c1p = g_conv1 + b * 16384;

        // zero both padded buffers
        for (int e = tid; e < 9248; e += NT) s_raw[e] = 0.0f;
        __syncthreads();

        // --- LN1 stats + normalize + 2x2 pool -> SA (64x64 in 68x68) ---
        float s = 0.0f, ss = 0.0f;
        for (int e = tid; e < 4096; e += NT) {
            float4 v = ((const float4*)c1p)[e];
            s += v.x + v.y + v.z + v.w;
            ss += v.x * v.x + v.y * v.y + v.z * v.z + v.w * v.w;
        }
        float2 st = bstats(s, ss);
        float mu = st.x * (1.0f / 16384.0f);
        float rstd = rsqrtf(st.y * (1.0f / 16384.0f) - mu * mu + 1e-5f);
        for (int p = tid; p < 4096; p += NT) {
            int io = p >> 6, jo = p & 63;
            float m = -CUDART_INF_F;
#pragma unroll
            for (int di = 0; di < 2; ++di)
#pragma unroll
                for (int dj = 0; dj < 2; ++dj) {
                    int q = (2 * io + di) * 128 + 2 * jo + dj;
                    float v = (c1p[q] - mu) * rstd * __ldg(g1 + q) + __ldg(be1 + q);
                    m = fmaxf(m, v);
                }
            SA[(io + 2) * 68 + jo + 2] = m;
        }
        __syncthreads();

        // --- conv2 (64x64, K=5) SA -> SB, stats fused ---
        s = ss = 0.0f;
        for (int p = tid; p < 4096; p += NT) {
            int i = p >> 6, j = p & 63;
            float4 wq[7];
            const float4* wv2 = (const float4*)(wp + OFF_W2 + p * 32);
#pragma unroll
            for (int t = 0; t < 7; ++t) wq[t] = wv2[t];
            const float* wf = (const float*)wq;
            const float* src = SA + i * 68 + j;
            float acc = __ldg(b2 + p);
#pragma unroll
            for (int u = 0; u < 5; ++u)
#pragma unroll
                for (int v = 0; v < 5; ++v)
                    acc = fmaf(src[u * 68 + v], wf[u * 5 + v], acc);
            acc = fmaxf(acc, 0.0f);
            SB[(i + 2) * 68 + j + 2] = acc;
            s += acc; ss += acc * acc;
        }
        st = bstats(s, ss);
        mu = st.x * (1.0f / 4096.0f);
        rstd = rsqrtf(st.y * (1.0f / 4096.0f) - mu * mu + 1e-5f);
        for (int p = tid; p < 4096; p += NT) {
            int idx = ((p >> 6) + 2) * 68 + (p & 63) + 2;
            SB[idx] = (SB[idx] - mu) * rstd * __ldg(g2 + p) + __ldg(be2 + p);
        }
        __syncthreads();

        // --- conv3 (64x64, K=5) SB -> SA, stats fused ---
        s = ss = 0.0f;
        for (int p = tid; p < 4096; p += NT) {
            int i = p >> 6, j = p & 63;
            float4 wq[7];
            const float4* wv3 = (const float4*)(wp + OFF_W3 + p * 32);
#pragma unroll
            for (int t = 0; t < 7; ++t) wq[t] = wv3[t];
            const float* wf = (const float*)wq;
            const float* src = SB + i * 68 + j;
            float acc = __ldg(b3 + p);
#pragma unroll
            for (int u = 0; u < 5; ++u)
#pragma unroll
                for (int v = 0; v < 5; ++v)
                    acc = fmaf(src[u * 68 + v], wf[u * 5 + v], acc);
            acc = fmaxf(acc, 0.0f);
            SA[(i + 2) * 68 + j + 2] = acc;
            s += acc; ss += acc * acc;
        }
        st = bstats(s, ss);
        mu = st.x * (1.0f / 4096.0f);
        rstd = rsqrtf(st.y * (1.0f / 4096.0f) - mu * mu + 1e-5f);
        // LN3 + pool: SA(64x64) -> SB as 34x34 padded (zero halo)
        for (int e = tid; e < 1156; e += NT) {
            int i34 = e / 34, j34 = e - i34 * 34;
            if (i34 == 0 || i34 == 33 || j34 == 0 || j34 == 33) { SB[e] = 0.0f; continue; }
            int io = i34 - 1, jo = j34 - 1;
            float m = -CUDART_INF_F;
#pragma unroll
            for (int di = 0; di < 2; ++di)
#pragma unroll
                for (int dj = 0; dj < 2; ++dj) {
                    int gi = 2 * io + di, gj = 2 * jo + dj;
                    int q = gi * 64 + gj;
                    float v = (SA[(gi + 2) * 68 + gj + 2] - mu) * rstd * __ldg(g3 + q) + __ldg(be3 + q);
                    m = fmaxf(m, v);
                }
            SB[e] = m;
        }
        __syncthreads();

        // --- conv4 (32x32, K=3) SB34 -> SA34 (+halo zero), stats fused ---
        s = ss = 0.0f;
        for (int e = tid; e < 1156; e += NT) {
            int i34 = e / 34, j34 = e - i34 * 34;
            if (i34 == 0 || i34 == 33 || j34 == 0 || j34 == 33) { SA[e] = 0.0f; continue; }
            int io = i34 - 1, jo = j34 - 1;
            int p = io * 32 + jo;
            float4 wq[3];
            const float4* wv4 = (const float4*)(wp + OFF_W4 + p * 12);
#pragma unroll
            for (int t = 0; t < 3; ++t) wq[t] = wv4[t];
            const float* wf = (const float*)wq;
            const float* src = SB + io * 34 + jo;
            float acc = __ldg(b4 + p);
#pragma unroll
            for (int u = 0; u < 3; ++u)
#pragma unroll
                for (int v = 0; v < 3; ++v)
                    acc = fmaf(src[u * 34 + v], wf[u * 3 + v], acc);
            acc = fmaxf(acc, 0.0f);
            SA[e] = acc;
            s += acc; ss += acc * acc;
        }
        st = bstats(s, ss);
        mu = st.x * (1.0f / 1024.0f);
        rstd = rsqrtf(st.y * (1.0f / 1024.0f) - mu * mu + 1e-5f);
        for (int p = tid; p < 1024; p += NT) {
            int idx = ((p >> 5) + 1) * 34 + (p & 31) + 1;
            SA[idx] = (SA[idx] - mu) * rstd * __ldg(g4 + p) + __ldg(be4 + p);
        }
        __syncthreads();

        // --- conv5 (32x32, K=3) SA34 -> SB34 interior (halo already 0), stats fused ---
        s = ss = 0.0f;
        for (int p = tid; p < 1024; p += NT) {
            int i = p >> 5, j = p & 31;
            float4 wq[3];
            const float4* wv5 = (const float4*)(wp + OFF_W5 + p * 12);
#pragma unroll
            for (int t = 0; t < 3; ++t) wq[t] = wv5[t];
            const float* wf = (const float*)wq;
            const float* src = SA + i * 34 + j;
            float acc = __ldg(b5 + p);
#pragma unroll
            for (int u = 0; u < 3; ++u)
#pragma unroll
                for (int v = 0; v < 3; ++v)
                    acc = fmaf(src[u * 34 + v], wf[u * 3 + v], acc);
            acc = fmaxf(acc, 0.0f);
            SB[(i + 1) * 34 + j + 1] = acc;
            s += acc; ss += acc * acc;
        }
        st = bstats(s, ss);
        mu = st.x * (1.0f / 1024.0f);
        rstd = rsqrtf(st.y * (1.0f / 1024.0f) - mu * mu + 1e-5f);
        // LN5 + pool: SB34 -> SA as 18x18 padded (zero halo)
        for (int e = tid; e < 324; e += NT) {
            int i18 = e / 18, j18 = e - i18 * 18;
            if (i18 == 0 || i18 == 17 || j18 == 0 || j18 == 17) { SA[e] = 0.0f; continue; }
            int io = i18 - 1, jo = j18 - 1;
            float m = -CUDART_INF_F;
#pragma unroll
            for (int di = 0; di < 2; ++di)
#pragma unroll
                for (int dj = 0; dj < 2; ++dj) {
                    int gi = 2 * io + di, gj = 2 * jo + dj;
                    int q = gi * 32 + gj;
                    float v = (SB[(gi + 1) * 34 + gj + 1] - mu) * rstd * __ldg(g5 + q) + __ldg(be5 + q);
                    m = fmaxf(m, v);
                }
            SA[e] = m;
        }
        __syncthreads();

        // --- conv6 (16x16, K=3) SA18 -> SB flat [0..256), stats fused ---
        s = ss = 0.0f;
        for (int p = tid; p < 256; p += NT) {
            int i = p >> 4, j = p & 15;
            float4 wq[3];
            const float4* wv6 = (const float4*)(wp + OFF_W6 + p * 12);
#pragma unroll
            for (int t = 0; t < 3; ++t) wq[t] = wv6[t];
            const float* wf = (const float*)wq;
            const float* src = SA + i * 18 + j;
            float acc = __ldg(b6 + p);
#pragma unroll
            for (int u = 0; u < 3; ++u)
#pragma unroll
                for (int v = 0; v < 3; ++v)
                    acc = fmaf(src[u * 18 + v], wf[u * 3 + v], acc);
            acc = fmaxf(acc, 0.0f);
            SB[p] = acc;
            s += acc; ss += acc * acc;
        }
        st = bstats(s, ss);
        mu = st.x * (1.0f / 256.0f);
        rstd = rsqrtf(st.y * (1.0f / 256.0f) - mu * mu + 1e-5f);
        for (int p = tid; p < 256; p += NT)
            g_h[b * 256 + p] = (SB[p] - mu) * rstd * __ldg(g6 + p) + __ldg(be6 + p);
    }
    grid_sync(gen);

    // ===== Phase 3: FC (2048 warps = 8 row-groups x 256 output-quads) =====
    {
        const int warp = bid * 16 + (tid >> 5);
        const int lane = tid & 31;
        const int rg = warp >> 8;       // 0..7
        const int oq = warp & 255;      // 0..255
        float hr[8][8];
        const float* hp = g_h + rg * 2048 + lane * 8;
#pragma unroll
        for (int r = 0; r < 8; ++r) {
            float4 a = *(const float4*)(hp + r * 256);
            float4 c = *(const float4*)(hp + r * 256 + 4);
            hr[r][0] = a.x; hr[r][1] = a.y; hr[r][2] = a.z; hr[r][3] = a.w;
            hr[r][4] = c.x; hr[r][5] = c.y; hr[r][6] = c.z; hr[r][7] = c.w;
        }
#pragma unroll
        for (int t = 0; t < 4; ++t) {
            int o = oq * 4 + t;
            const float4* wr = (const float4*)(fcw + o * 256 + lane * 8);
            float4 wa = __ldg(wr), wb = __ldg(wr + 1);
            float a[8];
#pragma unroll
            for (int r = 0; r < 8; ++r) {
                a[r] = hr[r][0] * wa.x + hr[r][1] * wa.y + hr[r][2] * wa.z + hr[r][3] * wa.w
                     + hr[r][4] * wb.x + hr[r][5] * wb.y + hr[r][6] * wb.z + hr[r][7] * wb.w;
            }
#pragma unroll
            for (int r = 0; r < 8; ++r)
#pragma unroll
                for (int off = 16; off; off >>= 1)
                    a[r] += __shfl_down_sync(0xFFFFFFFFu, a[r], off);
            if (lane == 0) {
                float bo = __ldg(fcb + o);
#pragma unroll
                for (int r = 0; r < 8; ++r)
                    g_logits[(rg * 8 + r) * 1024 + o] = a[r] + bo;
            }
        }
    }
    grid_sync(gen);

    // ===== Phase 4: softmax (blocks 0..63, one row each) =====
    if (bid < 64) {
        __shared__ float red[16];
        const int wid = tid >> 5, lid = tid & 31;
        const float* row = g_logits + bid * 1024;
        float v0 = row[tid], v1 = row[512 + tid];
        float mx = fmaxf(v0, v1);
#pragma unroll
        for (int o = 16; o; o >>= 1) mx = fmaxf(mx, __shfl_xor_sync(0xFFFFFFFFu, mx, o));
        if (lid == 0) red[wid] = mx;
        __syncthreads();
        mx = red[0];
#pragma unroll
        for (int w = 1; w < 16; ++w) mx = fmaxf(mx, red[w]);
        __syncthreads();

        float e0 = __expf(v0 - mx), e1 = __expf(v1 - mx);
        float ps = e0 + e1;
#pragma unroll
        for (int o = 16; o; o >>= 1) ps += __shfl_xor_sync(0xFFFFFFFFu, ps, o);
        if (lid == 0) red[wid] = ps;
        __syncthreads();
        float tot = 0.0f;
#pragma unroll
        for (int w = 0; w < 16; ++w) tot += red[w];
        float inv = 1.0f / tot;
        out[bid * 1024 + tid] = e0 * inv;
        out[bid * 1024 + 512 + tid] = e1 * inv;
    }
}

// ---------------------------------------------------------------------------
extern "C" void kernel_launch(void* const* d_in, const int* in_sizes, int n_in,
                              void* d_out, int out_size) {
    (void)in_sizes; (void)n_in; (void)out_size;

    const float* x = (const float*)d_in[0];
    const float* P[27];
    for (int i = 0; i < 27; ++i) P[i] = (const float*)d_in[i];

    allnet_kernel<<<NB, NT>>>(
        x,
        P[1], P[2], P[3], P[4],
        P[5], P[6], P[7], P[8],
        P[9], P[10], P[11], P[12],
        P[13], P[14], P[15], P[16],
        P[17], P[18], P[19], P[20],
        P[21], P[22], P[23], P[24],
        P[25], P[26],
        (float*)d_out);
}

// round 6
// speedup vs baseline: 1.4507x; 1.4507x over previous
#include <cuda_runtime.h>
#include <math_constants.h>

#define BATCH 64

// scratch
__device__ float g_conv1[BATCH * 16384];
__device__ float g_h[BATCH * 256];
__device__ float g_logits[BATCH * 1024];
__device__ float g_wpack[1141760];

// packed-weight offsets (floats)
#define OFF_W1 0          // 16384 pos * 52
#define OFF_W2 851968     // 4096 * 32
#define OFF_W3 983040     // 4096 * 32
#define OFF_W4 1114112    // 1024 * 12
#define OFF_W5 1126400    // 1024 * 12
#define OFF_W6 1138688    // 256 * 12

// ---------------------------------------------------------------------------
// Repack weights: pad per-position weights to float4-aligned strides.
// ---------------------------------------------------------------------------
__global__ void repack_kernel(const float* __restrict__ w1, const float* __restrict__ w2,
                              const float* __restrict__ w3, const float* __restrict__ w4,
                              const float* __restrict__ w5, const float* __restrict__ w6,
                              float* __restrict__ wp) {
    int tid = blockIdx.x * blockDim.x + threadIdx.x;
    int nt = gridDim.x * blockDim.x;
    for (int i = tid; i < 16384 * 49; i += nt) { int p = i / 49, k = i - p * 49; wp[OFF_W1 + p * 52 + k] = w1[i]; }
    for (int i = tid; i < 4096 * 25; i += nt)  { int p = i / 25, k = i - p * 25; wp[OFF_W2 + p * 32 + k] = w2[i]; }
    for (int i = tid; i < 4096 * 25; i += nt)  { int p = i / 25, k = i - p * 25; wp[OFF_W3 + p * 32 + k] = w3[i]; }
    for (int i = tid; i < 1024 * 9; i += nt)   { int p = i / 9,  k = i - p * 9;  wp[OFF_W4 + p * 12 + k] = w4[i]; }
    for (int i = tid; i < 1024 * 9; i += nt)   { int p = i / 9,  k = i - p * 9;  wp[OFF_W5 + p * 12 + k] = w5[i]; }
    for (int i = tid; i < 256 * 9; i += nt)    { int p = i / 9,  k = i - p * 9;  wp[OFF_W6 + p * 12 + k] = w6[i]; }
}

// ---------------------------------------------------------------------------
// Conv1: 128x128, K=7, pad=3, + ReLU. Block = 8x32 tile x 8-batch group.
// Weights in 13 float4 regs reused across 8 batches; 4-batch ILP chains.
// Grid: (64 tiles, 8 batch groups), 256 threads.
// ---------------------------------------------------------------------------
__global__ void __launch_bounds__(256) conv1_kernel(const float* __restrict__ x,
                                                    const float* __restrict__ wp,
                                                    const float* __restrict__ b1,
                                                    float* __restrict__ out) {
    __shared__ float sm[8][14][38];   // 8 batches x (8+6) x (32+6)
    const int tile = blockIdx.x;
    const int bg = blockIdx.y;
    const int tx = tile & 3, ty = tile >> 2;
    const int tj0 = tx * 32, ti0 = ty * 8;
    const int tid = threadIdx.x;

    for (int e = tid; e < 8 * 14 * 38; e += 256) {
        int bb = e / (14 * 38);
        int rem = e - bb * (14 * 38);
        int r = rem / 38, c = rem - r * 38;
        int gi = ti0 - 3 + r, gj = tj0 - 3 + c;
        float v = 0.0f;
        if ((unsigned)gi < 128u && (unsigned)gj < 128u)
            v = x[(bg * 8 + bb) * 16384 + gi * 128 + gj];
        sm[bb][r][c] = v;
    }

    const int ti = tid >> 5, tj = tid & 31;
    const int p = (ti0 + ti) * 128 + (tj0 + tj);
    float4 wreg[13];
    const float4* wv = (const float4*)(wp + OFF_W1 + p * 52);
#pragma unroll
    for (int t = 0; t < 13; ++t) wreg[t] = __ldg(wv + t);
    const float* wf = (const float*)wreg;
    const float bias = __ldg(b1 + p);
    __syncthreads();

#pragma unroll
    for (int bb = 0; bb < 8; bb += 4) {
        float a0 = bias, a1 = bias, a2 = bias, a3 = bias;
#pragma unroll
        for (int u = 0; u < 7; ++u)
#pragma unroll
            for (int v = 0; v < 7; ++v) {
                float wv_ = wf[u * 7 + v];
                a0 = fmaf(sm[bb + 0][ti + u][tj + v], wv_, a0);
                a1 = fmaf(sm[bb + 1][ti + u][tj + v], wv_, a1);
                a2 = fmaf(sm[bb + 2][ti + u][tj + v], wv_, a2);
                a3 = fmaf(sm[bb + 3][ti + u][tj + v], wv_, a3);
            }
        out[(bg * 8 + bb + 0) * 16384 + p] = fmaxf(a0, 0.0f);
        out[(bg * 8 + bb + 1) * 16384 + p] = fmaxf(a1, 0.0f);
        out[(bg * 8 + bb + 2) * 16384 + p] = fmaxf(a2, 0.0f);
        out[(bg * 8 + bb + 3) * 16384 + p] = fmaxf(a3, 0.0f);
    }
}

// ---------------------------------------------------------------------------
// block stats over 1024 threads = 32 warps
// ---------------------------------------------------------------------------
__device__ __forceinline__ float2 bstats(float s, float ss) {
    __shared__ float r0[32], r1[32];
    int tid = threadIdx.x, wid = tid >> 5, lid = tid & 31;
#pragma unroll
    for (int o = 16; o; o >>= 1) {
        s += __shfl_down_sync(0xFFFFFFFFu, s, o);
        ss += __shfl_down_sync(0xFFFFFFFFu, ss, o);
    }
    if (lid == 0) { r0[wid] = s; r1[wid] = ss; }
    __syncthreads();
    if (wid == 0) {
        s = r0[lid];
        ss = r1[lid];
#pragma unroll
        for (int o = 16; o; o >>= 1) {
            s += __shfl_down_sync(0xFFFFFFFFu, s, o);
            ss += __shfl_down_sync(0xFFFFFFFFu, ss, o);
        }
        if (lid == 0) { r0[0] = s; r1[0] = ss; }
    }
    __syncthreads();
    float2 res = make_float2(r0[0], r1[0]);
    __syncthreads();
    return res;
}

// ---------------------------------------------------------------------------
// Mega: block per sample (grid=64, 1024 threads). Padded smem layouts so
// conv inner loops have zero predicates; LN stats fused into conv writes.
// ---------------------------------------------------------------------------
#define MT 1024
__global__ void __launch_bounds__(MT) mega_kernel(
    const float* __restrict__ c1, const float* __restrict__ g1, const float* __restrict__ be1,
    const float* __restrict__ wp,
    const float* __restrict__ b2, const float* __restrict__ g2, const float* __restrict__ be2,
    const float* __restrict__ b3, const float* __restrict__ g3, const float* __restrict__ be3,
    const float* __restrict__ b4, const float* __restrict__ g4, const float* __restrict__ be4,
    const float* __restrict__ b5, const float* __restrict__ g5, const float* __restrict__ be5,
    const float* __restrict__ b6, const float* __restrict__ g6, const float* __restrict__ be6,
    float* __restrict__ hout) {
    __shared__ float s_raw[9248];   // SA: 68x68 padded, SB: 68x68 padded
    float* SA = s_raw;
    float* SB = s_raw + 4624;
    const int tid = threadIdx.x;
    const int b = blockIdx.x;
    const float* c1p = c1 + b * 16384;

    // zero both padded buffers (halo regions must be 0)
    for (int e = tid; e < 9248; e += MT) s_raw[e] = 0.0f;
    __syncthreads();

    // --- LN1 stats + normalize + 2x2 pool -> SA (64x64 in 68-stride, +2 off) ---
    float s = 0.0f, ss = 0.0f;
    for (int e = tid; e < 4096; e += MT) {
        float4 v = ((const float4*)c1p)[e];
        s += v.x + v.y + v.z + v.w;
        ss += v.x * v.x + v.y * v.y + v.z * v.z + v.w * v.w;
    }
    float2 st = bstats(s, ss);
    float mu = st.x * (1.0f / 16384.0f);
    float rstd = rsqrtf(st.y * (1.0f / 16384.0f) - mu * mu + 1e-5f);
    for (int p = tid; p < 4096; p += MT) {
        int io = p >> 6, jo = p & 63;
        float m = -CUDART_INF_F;
#pragma unroll
        for (int di = 0; di < 2; ++di)
#pragma unroll
            for (int dj = 0; dj < 2; ++dj) {
                int q = (2 * io + di) * 128 + 2 * jo + dj;
                float v = (c1p[q] - mu) * rstd * __ldg(g1 + q) + __ldg(be1 + q);
                m = fmaxf(m, v);
            }
        SA[(io + 2) * 68 + jo + 2] = m;
    }
    __syncthreads();

    // --- conv2 (64x64, K=5) SA -> SB, stats fused ---
    s = ss = 0.0f;
    for (int p = tid; p < 4096; p += MT) {
        int i = p >> 6, j = p & 63;
        float4 wq[7];
        const float4* wv2 = (const float4*)(wp + OFF_W2 + p * 32);
#pragma unroll
        for (int t = 0; t < 7; ++t) wq[t] = __ldg(wv2 + t);
        const float* wf = (const float*)wq;
        const float* src = SA + i * 68 + j;
        float acc = __ldg(b2 + p);
#pragma unroll
        for (int u = 0; u < 5; ++u)
#pragma unroll
            for (int v = 0; v < 5; ++v)
                acc = fmaf(src[u * 68 + v], wf[u * 5 + v], acc);
        acc = fmaxf(acc, 0.0f);
        SB[(i + 2) * 68 + j + 2] = acc;
        s += acc; ss += acc * acc;
    }
    st = bstats(s, ss);
    mu = st.x * (1.0f / 4096.0f);
    rstd = rsqrtf(st.y * (1.0f / 4096.0f) - mu * mu + 1e-5f);
    for (int p = tid; p < 4096; p += MT) {
        int idx = ((p >> 6) + 2) * 68 + (p & 63) + 2;
        SB[idx] = (SB[idx] - mu) * rstd * __ldg(g2 + p) + __ldg(be2 + p);
    }
    __syncthreads();

    // --- conv3 (64x64, K=5) SB -> SA, stats fused ---
    s = ss = 0.0f;
    for (int p = tid; p < 4096; p += MT) {
        int i = p >> 6, j = p & 63;
        float4 wq[7];
        const float4* wv3 = (const float4*)(wp + OFF_W3 + p * 32);
#pragma unroll
        for (int t = 0; t < 7; ++t) wq[t] = __ldg(wv3 + t);
        const float* wf = (const float*)wq;
        const float* src = SB + i * 68 + j;
        float acc = __ldg(b3 + p);
#pragma unroll
        for (int u = 0; u < 5; ++u)
#pragma unroll
            for (int v = 0; v < 5; ++v)
                acc = fmaf(src[u * 68 + v], wf[u * 5 + v], acc);
        acc = fmaxf(acc, 0.0f);
        SA[(i + 2) * 68 + j + 2] = acc;
        s += acc; ss += acc * acc;
    }
    st = bstats(s, ss);
    mu = st.x * (1.0f / 4096.0f);
    rstd = rsqrtf(st.y * (1.0f / 4096.0f) - mu * mu + 1e-5f);
    // LN3 + pool: SA(64x64) -> SB as 34x34 padded (zero halo)
    for (int e = tid; e < 1156; e += MT) {
        int i34 = e / 34, j34 = e - i34 * 34;
        if (i34 == 0 || i34 == 33 || j34 == 0 || j34 == 33) { SB[e] = 0.0f; continue; }
        int io = i34 - 1, jo = j34 - 1;
        float m = -CUDART_INF_F;
#pragma unroll
        for (int di = 0; di < 2; ++di)
#pragma unroll
            for (int dj = 0; dj < 2; ++dj) {
                int gi = 2 * io + di, gj = 2 * jo + dj;
                int q = gi * 64 + gj;
                float v = (SA[(gi + 2) * 68 + gj + 2] - mu) * rstd * __ldg(g3 + q) + __ldg(be3 + q);
                m = fmaxf(m, v);
            }
        SB[e] = m;
    }
    __syncthreads();

    // --- conv4 (32x32, K=3) SB34 -> SA34 (+halo zero), stats fused ---
    s = ss = 0.0f;
    for (int e = tid; e < 1156; e += MT) {
        int i34 = e / 34, j34 = e - i34 * 34;
        if (i34 == 0 || i34 == 33 || j34 == 0 || j34 == 33) { SA[e] = 0.0f; continue; }
        int io = i34 - 1, jo = j34 - 1;
        int p = io * 32 + jo;
        float4 wq[3];
        const float4* wv4 = (const float4*)(wp + OFF_W4 + p * 12);
#pragma unroll
        for (int t = 0; t < 3; ++t) wq[t] = __ldg(wv4 + t);
        const float* wf = (const float*)wq;
        const float* src = SB + io * 34 + jo;
        float acc = __ldg(b4 + p);
#pragma unroll
        for (int u = 0; u < 3; ++u)
#pragma unroll
            for (int v = 0; v < 3; ++v)
                acc = fmaf(src[u * 34 + v], wf[u * 3 + v], acc);
        acc = fmaxf(acc, 0.0f);
        SA[e] = acc;
        s += acc; ss += acc * acc;
    }
    st = bstats(s, ss);
    mu = st.x * (1.0f / 1024.0f);
    rstd = rsqrtf(st.y * (1.0f / 1024.0f) - mu * mu + 1e-5f);
    for (int p = tid; p < 1024; p += MT) {
        int idx = ((p >> 5) + 1) * 34 + (p & 31) + 1;
        SA[idx] = (SA[idx] - mu) * rstd * __ldg(g4 + p) + __ldg(be4 + p);
    }
    __syncthreads();

    // --- conv5 (32x32, K=3) SA34 -> SB34 interior, stats fused ---
    s = ss = 0.0f;
    for (int p = tid; p < 1024; p += MT) {
        int i = p >> 5, j = p & 31;
        float4 wq[3];
        const float4* wv5 = (const float4*)(wp + OFF_W5 + p * 12);
#pragma unroll
        for (int t = 0; t < 3; ++t) wq[t] = __ldg(wv5 + t);
        const float* wf = (const float*)wq;
        const float* src = SA + i * 34 + j;
        float acc = __ldg(b5 + p);
#pragma unroll
        for (int u = 0; u < 3; ++u)
#pragma unroll
            for (int v = 0; v < 3; ++v)
                acc = fmaf(src[u * 34 + v], wf[u * 3 + v], acc);
        acc = fmaxf(acc, 0.0f);
        SB[(i + 1) * 34 + j + 1] = acc;
        s += acc; ss += acc * acc;
    }
    st = bstats(s, ss);
    mu = st.x * (1.0f / 1024.0f);
    rstd = rsqrtf(st.y * (1.0f / 1024.0f) - mu * mu + 1e-5f);
    // LN5 + pool: SB34 -> SA as 18x18 padded (zero halo)
    for (int e = tid; e < 324; e += MT) {
        int i18 = e / 18, j18 = e - i18 * 18;
        if (i18 == 0 || i18 == 17 || j18 == 0 || j18 == 17) { SA[e] = 0.0f; continue; }
        int io = i18 - 1, jo = j18 - 1;
        float m = -CUDART_INF_F;
#pragma unroll
        for (int di = 0; di < 2; ++di)
#pragma unroll
            for (int dj = 0; dj < 2; ++dj) {
                int gi = 2 * io + di, gj = 2 * jo + dj;
                int q = gi * 32 + gj;
                float v = (SB[(gi + 1) * 34 + gj + 1] - mu) * rstd * __ldg(g5 + q) + __ldg(be5 + q);
                m = fmaxf(m, v);
            }
        SA[e] = m;
    }
    __syncthreads();

    // --- conv6 (16x16, K=3) SA18 -> SB flat [0..256), stats fused ---
    s = ss = 0.0f;
    for (int p = tid; p < 256; p += MT) {
        int i = p >> 4, j = p & 15;
        float4 wq[3];
        const float4* wv6 = (const float4*)(wp + OFF_W6 + p * 12);
#pragma unroll
        for (int t = 0; t < 3; ++t) wq[t] = __ldg(wv6 + t);
        const float* wf = (const float*)wq;
        const float* src = SA + i * 18 + j;
        float acc = __ldg(b6 + p);
#pragma unroll
        for (int u = 0; u < 3; ++u)
#pragma unroll
            for (int v = 0; v < 3; ++v)
                acc = fmaf(src[u * 18 + v], wf[u * 3 + v], acc);
        acc = fmaxf(acc, 0.0f);
        SB[p] = acc;
        s += acc; ss += acc * acc;
    }
    st = bstats(s, ss);
    mu = st.x * (1.0f / 256.0f);
    rstd = rsqrtf(st.y * (1.0f / 256.0f) - mu * mu + 1e-5f);
    for (int p = tid; p < 256; p += MT)
        hout[b * 256 + p] = (SB[p] - mu) * rstd * __ldg(g6 + p) + __ldg(be6 + p);
}

// ---------------------------------------------------------------------------
// FC, shuffle-free: thread-per-output, 4-batch accumulators.
// Grid (4 col-tiles x 16 row-groups), 256 threads. Each thread streams its
// private fcw row as float4 (L1-resident across iterations), h from smem.
// ---------------------------------------------------------------------------
__global__ void __launch_bounds__(256) fc_kernel(const float* __restrict__ h,
                                                 const float* __restrict__ fcw,
                                                 const float* __restrict__ fcb,
                                                 float* __restrict__ logits) {
    __shared__ float hs[4][256];
    const int ct = blockIdx.x, rg = blockIdx.y;
    const int tid = threadIdx.x;

    for (int e = tid; e < 1024; e += 256) hs[e >> 8][e & 255] = h[rg * 1024 + e];
    __syncthreads();

    const int o = ct * 256 + tid;
    const float4* wr = (const float4*)(fcw + o * 256);
    float a0 = 0.0f, a1 = 0.0f, a2 = 0.0f, a3 = 0.0f;
#pragma unroll 8
    for (int kk = 0; kk < 64; ++kk) {
        float4 wv = __ldg(wr + kk);
        int k = kk * 4;
        a0 = fmaf(hs[0][k], wv.x, a0); a0 = fmaf(hs[0][k + 1], wv.y, a0);
        a0 = fmaf(hs[0][k + 2], wv.z, a0); a0 = fmaf(hs[0][k + 3], wv.w, a0);
        a1 = fmaf(hs[1][k], wv.x, a1); a1 = fmaf(hs[1][k + 1], wv.y, a1);
        a1 = fmaf(hs[1][k + 2], wv.z, a1); a1 = fmaf(hs[1][k + 3], wv.w, a1);
        a2 = fmaf(hs[2][k], wv.x, a2); a2 = fmaf(hs[2][k + 1], wv.y, a2);
        a2 = fmaf(hs[2][k + 2], wv.z, a2); a2 = fmaf(hs[2][k + 3], wv.w, a2);
        a3 = fmaf(hs[3][k], wv.x, a3); a3 = fmaf(hs[3][k + 1], wv.y, a3);
        a3 = fmaf(hs[3][k + 2], wv.z, a3); a3 = fmaf(hs[3][k + 3], wv.w, a3);
    }
    float bo = __ldg(fcb + o);
    logits[(rg * 4 + 0) * 1024 + o] = a0 + bo;
    logits[(rg * 4 + 1) * 1024 + o] = a1 + bo;
    logits[(rg * 4 + 2) * 1024 + o] = a2 + bo;
    logits[(rg * 4 + 3) * 1024 + o] = a3 + bo;
}

// ---------------------------------------------------------------------------
// Softmax over 1024 per row. Grid=64, 256 threads.
// ---------------------------------------------------------------------------
__global__ void __launch_bounds__(256) softmax_kernel(const float* __restrict__ logits,
                                                      float* __restrict__ out) {
    __shared__ float red[8];
    const int b = blockIdx.x, tid = threadIdx.x, wid = tid >> 5, lid = tid & 31;
    const float* row = logits + b * 1024;

    float v[4];
#pragma unroll
    for (int t = 0; t < 4; ++t) v[t] = row[t * 256 + tid];
    float mx = fmaxf(fmaxf(v[0], v[1]), fmaxf(v[2], v[3]));
#pragma unroll
    for (int o = 16; o; o >>= 1) mx = fmaxf(mx, __shfl_xor_sync(0xFFFFFFFFu, mx, o));
    if (lid == 0) red[wid] = mx;
    __syncthreads();
    mx = red[0];
#pragma unroll
    for (int w = 1; w < 8; ++w) mx = fmaxf(mx, red[w]);
    __syncthreads();

    float e[4], ps = 0.0f;
#pragma unroll
    for (int t = 0; t < 4; ++t) { e[t] = __expf(v[t] - mx); ps += e[t]; }
#pragma unroll
    for (int o = 16; o; o >>= 1) ps += __shfl_xor_sync(0xFFFFFFFFu, ps, o);
    if (lid == 0) red[wid] = ps;
    __syncthreads();
    float tot = 0.0f;
#pragma unroll
    for (int w = 0; w < 8; ++w) tot += red[w];
    float inv = 1.0f / tot;
#pragma unroll
    for (int t = 0; t < 4; ++t) out[b * 1024 + t * 256 + tid] = e[t] * inv;
}

// ---------------------------------------------------------------------------
extern "C" void kernel_launch(void* const* d_in, const int* in_sizes, int n_in,
                              void* d_out, int out_size) {
    (void)in_sizes; (void)n_in; (void)out_size;

    const float* x = (const float*)d_in[0];
    const float* w[7];
    const float* bi[7];
    const float* gg[7];
    const float* bb[7];
    for (int L = 1; L <= 6; ++L) {
        w[L]  = (const float*)d_in[1 + 4 * (L - 1) + 0];
        bi[L] = (const float*)d_in[1 + 4 * (L - 1) + 1];
        gg[L] = (const float*)d_in[1 + 4 * (L - 1) + 2];
        bb[L] = (const float*)d_in[1 + 4 * (L - 1) + 3];
    }
    const float* fcw = (const float*)d_in[25];
    const float* fcb = (const float*)d_in[26];
    float* out = (float*)d_out;

    float *c1, *h, *lg, *wp;
    cudaGetSymbolAddress((void**)&c1, g_conv1);
    cudaGetSymbolAddress((void**)&h, g_h);
    cudaGetSymbolAddress((void**)&lg, g_logits);
    cudaGetSymbolAddress((void**)&wp, g_wpack);

    repack_kernel<<<256, 256>>>(w[1], w[2], w[3], w[4], w[5], w[6], wp);
    conv1_kernel<<<dim3(64, 8), 256>>>(x, wp, bi[1], c1);
    mega_kernel<<<64, MT>>>(c1, gg[1], bb[1], wp,
                            bi[2], gg[2], bb[2],
                            bi[3], gg[3], bb[3],
                            bi[4], gg[4], bb[4],
                            bi[5], gg[5], bb[5],
                            bi[6], gg[6], bb[6],
                            h);
    fc_kernel<<<dim3(4, 16), 256>>>(h, fcw, fcb, lg);
    softmax_kernel<<<64, 256>>>(lg, out);
}

// round 7
// speedup vs baseline: 1.4586x; 1.0055x over previous
#include <cuda_runtime.h>
#include <math_constants.h>

#define BATCH 64

// scratch
__device__ float g_conv1[BATCH * 16384];
__device__ float g_h[BATCH * 256];
__device__ float g_logits[BATCH * 1024];
__device__ float g_wpack[1141760];

// packed-weight offsets (floats)
#define OFF_W1 0          // 16384 pos * 52
#define OFF_W2 851968     // 4096 * 32
#define OFF_W3 983040     // 4096 * 32
#define OFF_W4 1114112    // 1024 * 12
#define OFF_W5 1126400    // 1024 * 12
#define OFF_W6 1138688    // 256 * 12

// ---------------------------------------------------------------------------
// Repack weights: pad per-position weights to float4-aligned strides.
// ---------------------------------------------------------------------------
__global__ void repack_kernel(const float* __restrict__ w1, const float* __restrict__ w2,
                              const float* __restrict__ w3, const float* __restrict__ w4,
                              const float* __restrict__ w5, const float* __restrict__ w6,
                              float* __restrict__ wp) {
    int tid = blockIdx.x * blockDim.x + threadIdx.x;
    int nt = gridDim.x * blockDim.x;
    for (int i = tid; i < 16384 * 49; i += nt) { int p = i / 49, k = i - p * 49; wp[OFF_W1 + p * 52 + k] = w1[i]; }
    for (int i = tid; i < 4096 * 25; i += nt)  { int p = i / 25, k = i - p * 25; wp[OFF_W2 + p * 32 + k] = w2[i]; }
    for (int i = tid; i < 4096 * 25; i += nt)  { int p = i / 25, k = i - p * 25; wp[OFF_W3 + p * 32 + k] = w3[i]; }
    for (int i = tid; i < 1024 * 9; i += nt)   { int p = i / 9,  k = i - p * 9;  wp[OFF_W4 + p * 12 + k] = w4[i]; }
    for (int i = tid; i < 1024 * 9; i += nt)   { int p = i / 9,  k = i - p * 9;  wp[OFF_W5 + p * 12 + k] = w5[i]; }
    for (int i = tid; i < 256 * 9; i += nt)    { int p = i / 9,  k = i - p * 9;  wp[OFF_W6 + p * 12 + k] = w6[i]; }
}

// ---------------------------------------------------------------------------
// Conv1: 128x128, K=7, pad=3, + ReLU. Block = 8x32 tile x 8-batch group.
// Weights in 13 float4 regs reused across 8 batches; 4-batch ILP chains.
// Grid: (64 tiles, 8 batch groups), 256 threads.
// ---------------------------------------------------------------------------
__global__ void __launch_bounds__(256) conv1_kernel(const float* __restrict__ x,
                                                    const float* __restrict__ wp,
                                                    const float* __restrict__ b1,
                                                    float* __restrict__ out) {
    __shared__ float sm[8][14][38];   // 8 batches x (8+6) x (32+6)
    const int tile = blockIdx.x;
    const int bg = blockIdx.y;
    const int tx = tile & 3, ty = tile >> 2;
    const int tj0 = tx * 32, ti0 = ty * 8;
    const int tid = threadIdx.x;

    for (int e = tid; e < 8 * 14 * 38; e += 256) {
        int bb = e / (14 * 38);
        int rem = e - bb * (14 * 38);
        int r = rem / 38, c = rem - r * 38;
        int gi = ti0 - 3 + r, gj = tj0 - 3 + c;
        float v = 0.0f;
        if ((unsigned)gi < 128u && (unsigned)gj < 128u)
            v = x[(bg * 8 + bb) * 16384 + gi * 128 + gj];
        sm[bb][r][c] = v;
    }

    const int ti = tid >> 5, tj = tid & 31;
    const int p = (ti0 + ti) * 128 + (tj0 + tj);
    float4 wreg[13];
    const float4* wv = (const float4*)(wp + OFF_W1 + p * 52);
#pragma unroll
    for (int t = 0; t < 13; ++t) wreg[t] = __ldg(wv + t);
    const float* wf = (const float*)wreg;
    const float bias = __ldg(b1 + p);
    __syncthreads();

#pragma unroll
    for (int bb = 0; bb < 8; bb += 4) {
        float a0 = bias, a1 = bias, a2 = bias, a3 = bias;
#pragma unroll
        for (int u = 0; u < 7; ++u)
#pragma unroll
            for (int v = 0; v < 7; ++v) {
                float wv_ = wf[u * 7 + v];
                a0 = fmaf(sm[bb + 0][ti + u][tj + v], wv_, a0);
                a1 = fmaf(sm[bb + 1][ti + u][tj + v], wv_, a1);
                a2 = fmaf(sm[bb + 2][ti + u][tj + v], wv_, a2);
                a3 = fmaf(sm[bb + 3][ti + u][tj + v], wv_, a3);
            }
        out[(bg * 8 + bb + 0) * 16384 + p] = fmaxf(a0, 0.0f);
        out[(bg * 8 + bb + 1) * 16384 + p] = fmaxf(a1, 0.0f);
        out[(bg * 8 + bb + 2) * 16384 + p] = fmaxf(a2, 0.0f);
        out[(bg * 8 + bb + 3) * 16384 + p] = fmaxf(a3, 0.0f);
    }
}

// ---------------------------------------------------------------------------
// block stats over 1024 threads = 32 warps
// ---------------------------------------------------------------------------
__device__ __forceinline__ float2 bstats(float s, float ss) {
    __shared__ float r0[32], r1[32];
    int tid = threadIdx.x, wid = tid >> 5, lid = tid & 31;
#pragma unroll
    for (int o = 16; o; o >>= 1) {
        s += __shfl_down_sync(0xFFFFFFFFu, s, o);
        ss += __shfl_down_sync(0xFFFFFFFFu, ss, o);
    }
    if (lid == 0) { r0[wid] = s; r1[wid] = ss; }
    __syncthreads();
    if (wid == 0) {
        s = r0[lid];
        ss = r1[lid];
#pragma unroll
        for (int o = 16; o; o >>= 1) {
            s += __shfl_down_sync(0xFFFFFFFFu, s, o);
            ss += __shfl_down_sync(0xFFFFFFFFu, ss, o);
        }
        if (lid == 0) { r0[0] = s; r1[0] = ss; }
    }
    __syncthreads();
    float2 res = make_float2(r0[0], r1[0]);
    __syncthreads();
    return res;
}

// ---------------------------------------------------------------------------
// Mega: block per sample (grid=64, 1024 threads). Padded smem layouts so
// conv inner loops have zero predicates; LN stats fused into conv writes.
// ---------------------------------------------------------------------------
#define MT 1024
__global__ void __launch_bounds__(MT) mega_kernel(
    const float* __restrict__ c1, const float* __restrict__ g1, const float* __restrict__ be1,
    const float* __restrict__ wp,
    const float* __restrict__ b2, const float* __restrict__ g2, const float* __restrict__ be2,
    const float* __restrict__ b3, const float* __restrict__ g3, const float* __restrict__ be3,
    const float* __restrict__ b4, const float* __restrict__ g4, const float* __restrict__ be4,
    const float* __restrict__ b5, const float* __restrict__ g5, const float* __restrict__ be5,
    const float* __restrict__ b6, const float* __restrict__ g6, const float* __restrict__ be6,
    float* __restrict__ hout) {
    __shared__ float s_raw[9248];   // SA: 68x68 padded, SB: 68x68 padded
    float* SA = s_raw;
    float* SB = s_raw + 4624;
    const int tid = threadIdx.x;
    const int b = blockIdx.x;
    const float* c1p = c1 + b * 16384;

    // zero both padded buffers (halo regions must be 0)
    for (int e = tid; e < 9248; e += MT) s_raw[e] = 0.0f;
    __syncthreads();

    // --- LN1 stats + normalize + 2x2 pool -> SA (64x64 in 68-stride, +2 off) ---
    float s = 0.0f, ss = 0.0f;
    for (int e = tid; e < 4096; e += MT) {
        float4 v = ((const float4*)c1p)[e];
        s += v.x + v.y + v.z + v.w;
        ss += v.x * v.x + v.y * v.y + v.z * v.z + v.w * v.w;
    }
    float2 st = bstats(s, ss);
    float mu = st.x * (1.0f / 16384.0f);
    float rstd = rsqrtf(st.y * (1.0f / 16384.0f) - mu * mu + 1e-5f);
    for (int p = tid; p < 4096; p += MT) {
        int io = p >> 6, jo = p & 63;
        float m = -CUDART_INF_F;
#pragma unroll
        for (int di = 0; di < 2; ++di)
#pragma unroll
            for (int dj = 0; dj < 2; ++dj) {
                int q = (2 * io + di) * 128 + 2 * jo + dj;
                float v = (c1p[q] - mu) * rstd * __ldg(g1 + q) + __ldg(be1 + q);
                m = fmaxf(m, v);
            }
        SA[(io + 2) * 68 + jo + 2] = m;
    }
    __syncthreads();

    // --- conv2 (64x64, K=5) SA -> SB, stats fused ---
    s = ss = 0.0f;
    for (int p = tid; p < 4096; p += MT) {
        int i = p >> 6, j = p & 63;
        float4 wq[7];
        const float4* wv2 = (const float4*)(wp + OFF_W2 + p * 32);
#pragma unroll
        for (int t = 0; t < 7; ++t) wq[t] = __ldg(wv2 + t);
        const float* wf = (const float*)wq;
        const float* src = SA + i * 68 + j;
        float acc = __ldg(b2 + p);
#pragma unroll
        for (int u = 0; u < 5; ++u)
#pragma unroll
            for (int v = 0; v < 5; ++v)
                acc = fmaf(src[u * 68 + v], wf[u * 5 + v], acc);
        acc = fmaxf(acc, 0.0f);
        SB[(i + 2) * 68 + j + 2] = acc;
        s += acc; ss += acc * acc;
    }
    st = bstats(s, ss);
    mu = st.x * (1.0f / 4096.0f);
    rstd = rsqrtf(st.y * (1.0f / 4096.0f) - mu * mu + 1e-5f);
    for (int p = tid; p < 4096; p += MT) {
        int idx = ((p >> 6) + 2) * 68 + (p & 63) + 2;
        SB[idx] = (SB[idx] - mu) * rstd * __ldg(g2 + p) + __ldg(be2 + p);
    }
    __syncthreads();

    // --- conv3 (64x64, K=5) SB -> SA, stats fused ---
    s = ss = 0.0f;
    for (int p = tid; p < 4096; p += MT) {
        int i = p >> 6, j = p & 63;
        float4 wq[7];
        const float4* wv3 = (const float4*)(wp + OFF_W3 + p * 32);
#pragma unroll
        for (int t = 0; t < 7; ++t) wq[t] = __ldg(wv3 + t);
        const float* wf = (const float*)wq;
        const float* src = SB + i * 68 + j;
        float acc = __ldg(b3 + p);
#pragma unroll
        for (int u = 0; u < 5; ++u)
#pragma unroll
            for (int v = 0; v < 5; ++v)
                acc = fmaf(src[u * 68 + v], wf[u * 5 + v], acc);
        acc = fmaxf(acc, 0.0f);
        SA[(i + 2) * 68 + j + 2] = acc;
        s += acc; ss += acc * acc;
    }
    st = bstats(s, ss);
    mu = st.x * (1.0f / 4096.0f);
    rstd = rsqrtf(st.y * (1.0f / 4096.0f) - mu * mu + 1e-5f);
    // LN3 + pool: SA(64x64) -> SB as 34x34 padded (zero halo)
    for (int e = tid; e < 1156; e += MT) {
        int i34 = e / 34, j34 = e - i34 * 34;
        if (i34 == 0 || i34 == 33 || j34 == 0 || j34 == 33) { SB[e] = 0.0f; continue; }
        int io = i34 - 1, jo = j34 - 1;
        float m = -CUDART_INF_F;
#pragma unroll
        for (int di = 0; di < 2; ++di)
#pragma unroll
            for (int dj = 0; dj < 2; ++dj) {
                int gi = 2 * io + di, gj = 2 * jo + dj;
                int q = gi * 64 + gj;
                float v = (SA[(gi + 2) * 68 + gj + 2] - mu) * rstd * __ldg(g3 + q) + __ldg(be3 + q);
                m = fmaxf(m, v);
            }
        SB[e] = m;
    }
    __syncthreads();

    // --- conv4 (32x32, K=3) SB34 -> SA34 (+halo zero), stats fused ---
    s = ss = 0.0f;
    for (int e = tid; e < 1156; e += MT) {
        int i34 = e / 34, j34 = e - i34 * 34;
        if (i34 == 0 || i34 == 33 || j34 == 0 || j34 == 33) { SA[e] = 0.0f; continue; }
        int io = i34 - 1, jo = j34 - 1;
        int p = io * 32 + jo;
        float4 wq[3];
        const float4* wv4 = (const float4*)(wp + OFF_W4 + p * 12);
#pragma unroll
        for (int t = 0; t < 3; ++t) wq[t] = __ldg(wv4 + t);
        const float* wf = (const float*)wq;
        const float* src = SB + io * 34 + jo;
        float acc = __ldg(b4 + p);
#pragma unroll
        for (int u = 0; u < 3; ++u)
#pragma unroll
            for (int v = 0; v < 3; ++v)
                acc = fmaf(src[u * 34 + v], wf[u * 3 + v], acc);
        acc = fmaxf(acc, 0.0f);
        SA[e] = acc;
        s += acc; ss += acc * acc;
    }
    st = bstats(s, ss);
    mu = st.x * (1.0f / 1024.0f);
    rstd = rsqrtf(st.y * (1.0f / 1024.0f) - mu * mu + 1e-5f);
    for (int p = tid; p < 1024; p += MT) {
        int idx = ((p >> 5) + 1) * 34 + (p & 31) + 1;
        SA[idx] = (SA[idx] - mu) * rstd * __ldg(g4 + p) + __ldg(be4 + p);
    }
    __syncthreads();

    // --- conv5 (32x32, K=3) SA34 -> SB34 interior, stats fused ---
    s = ss = 0.0f;
    for (int p = tid; p < 1024; p += MT) {
        int i = p >> 5, j = p & 31;
        float4 wq[3];
        const float4* wv5 = (const float4*)(wp + OFF_W5 + p * 12);
#pragma unroll
        for (int t = 0; t < 3; ++t) wq[t] = __ldg(wv5 + t);
        const float* wf = (const float*)wq;
        const float* src = SA + i * 34 + j;
        float acc = __ldg(b5 + p);
#pragma unroll
        for (int u = 0; u < 3; ++u)
#pragma unroll
            for (int v = 0; v < 3; ++v)
                acc = fmaf(src[u * 34 + v], wf[u * 3 + v], acc);
        acc = fmaxf(acc, 0.0f);
        SB[(i + 1) * 34 + j + 1] = acc;
        s += acc; ss += acc * acc;
    }
    st = bstats(s, ss);
    mu = st.x * (1.0f / 1024.0f);
    rstd = rsqrtf(st.y * (1.0f / 1024.0f) - mu * mu + 1e-5f);
    // LN5 + pool: SB34 -> SA as 18x18 padded (zero halo)
    for (int e = tid; e < 324; e += MT) {
        int i18 = e / 18, j18 = e - i18 * 18;
        if (i18 == 0 || i18 == 17 || j18 == 0 || j18 == 17) { SA[e] = 0.0f; continue; }
        int io = i18 - 1, jo = j18 - 1;
        float m = -CUDART_INF_F;
#pragma unroll
        for (int di = 0; di < 2; ++di)
#pragma unroll
            for (int dj = 0; dj < 2; ++dj) {
                int gi = 2 * io + di, gj = 2 * jo + dj;
                int q = gi * 32 + gj;
                float v = (SB[(gi + 1) * 34 + gj + 1] - mu) * rstd * __ldg(g5 + q) + __ldg(be5 + q);
                m = fmaxf(m, v);
            }
        SA[e] = m;
    }
    __syncthreads();

    // --- conv6 (16x16, K=3) SA18 -> SB flat [0..256), stats fused ---
    s = ss = 0.0f;
    for (int p = tid; p < 256; p += MT) {
        int i = p >> 4, j = p & 15;
        float4 wq[3];
        const float4* wv6 = (const float4*)(wp + OFF_W6 + p * 12);
#pragma unroll
        for (int t = 0; t < 3; ++t) wq[t] = __ldg(wv6 + t);
        const float* wf = (const float*)wq;
        const float* src = SA + i * 18 + j;
        float acc = __ldg(b6 + p);
#pragma unroll
        for (int u = 0; u < 3; ++u)
#pragma unroll
            for (int v = 0; v < 3; ++v)
                acc = fmaf(src[u * 18 + v], wf[u * 3 + v], acc);
        acc = fmaxf(acc, 0.0f);
        SB[p] = acc;
        s += acc; ss += acc * acc;
    }
    st = bstats(s, ss);
    mu = st.x * (1.0f / 256.0f);
    rstd = rsqrtf(st.y * (1.0f / 256.0f) - mu * mu + 1e-5f);
    for (int p = tid; p < 256; p += MT)
        hout[b * 256 + p] = (SB[p] - mu) * rstd * __ldg(g6 + p) + __ldg(be6 + p);
}

// ---------------------------------------------------------------------------
// FC: logits[64,1024] = h[64,256] @ fcw.T + fcb.
// Grid = (32 col-tiles of 32 outputs, 16 row-groups of 4 rows), 256 threads.
// Warp computes 4 outputs x 4 rows; coalesced float4 fcw reads; h in regs.
// ---------------------------------------------------------------------------
__global__ void __launch_bounds__(256) fc_kernel(const float* __restrict__ h,
                                                 const float* __restrict__ fcw,
                                                 const float* __restrict__ fcb,
                                                 float* __restrict__ logits) {
    __shared__ float hs[4 * 256];
    const int ct = blockIdx.x, rg = blockIdx.y;
    const int tid = threadIdx.x, wid = tid >> 5, lid = tid & 31;

    for (int e = tid; e < 1024; e += 256) hs[e] = h[rg * 1024 + e];
    __syncthreads();

    float hr[4][8];
#pragma unroll
    for (int r = 0; r < 4; ++r)
#pragma unroll
        for (int c = 0; c < 8; ++c) hr[r][c] = hs[r * 256 + lid * 8 + c];

    const int obase = ct * 32 + wid * 4;
#pragma unroll
    for (int t = 0; t < 4; ++t) {
        int o = obase + t;
        const float4* wr = (const float4*)(fcw + o * 256 + lid * 8);
        float4 wa = __ldg(wr), wb = __ldg(wr + 1);
        float a[4];
#pragma unroll
        for (int r = 0; r < 4; ++r) {
            a[r] = hr[r][0] * wa.x + hr[r][1] * wa.y + hr[r][2] * wa.z + hr[r][3] * wa.w
                 + hr[r][4] * wb.x + hr[r][5] * wb.y + hr[r][6] * wb.z + hr[r][7] * wb.w;
        }
#pragma unroll
        for (int r = 0; r < 4; ++r)
#pragma unroll
            for (int off = 16; off; off >>= 1) a[r] += __shfl_down_sync(0xFFFFFFFFu, a[r], off);
        if (lid == 0) {
            float bo = __ldg(fcb + o);
#pragma unroll
            for (int r = 0; r < 4; ++r) logits[(rg * 4 + r) * 1024 + o] = a[r] + bo;
        }
    }
}

// ---------------------------------------------------------------------------
// Softmax over 1024 per row. Grid=64, 256 threads.
// ---------------------------------------------------------------------------
__global__ void __launch_bounds__(256) softmax_kernel(const float* __restrict__ logits,
                                                      float* __restrict__ out) {
    __shared__ float red[8];
    const int b = blockIdx.x, tid = threadIdx.x, wid = tid >> 5, lid = tid & 31;
    const float* row = logits + b * 1024;

    float v[4];
#pragma unroll
    for (int t = 0; t < 4; ++t) v[t] = row[t * 256 + tid];
    float mx = fmaxf(fmaxf(v[0], v[1]), fmaxf(v[2], v[3]));
#pragma unroll
    for (int o = 16; o; o >>= 1) mx = fmaxf(mx, __shfl_xor_sync(0xFFFFFFFFu, mx, o));
    if (lid == 0) red[wid] = mx;
    __syncthreads();
    mx = red[0];
#pragma unroll
    for (int w = 1; w < 8; ++w) mx = fmaxf(mx, red[w]);
    __syncthreads();

    float e[4], ps = 0.0f;
#pragma unroll
    for (int t = 0; t < 4; ++t) { e[t] = __expf(v[t] - mx); ps += e[t]; }
#pragma unroll
    for (int o = 16; o; o >>= 1) ps += __shfl_xor_sync(0xFFFFFFFFu, ps, o);
    if (lid == 0) red[wid] = ps;
    __syncthreads();
    float tot = 0.0f;
#pragma unroll
    for (int w = 0; w < 8; ++w) tot += red[w];
    float inv = 1.0f / tot;
#pragma unroll
    for (int t = 0; t < 4; ++t) out[b * 1024 + t * 256 + tid] = e[t] * inv;
}

// ---------------------------------------------------------------------------
extern "C" void kernel_launch(void* const* d_in, const int* in_sizes, int n_in,
                              void* d_out, int out_size) {
    (void)in_sizes; (void)n_in; (void)out_size;

    const float* x = (const float*)d_in[0];
    const float* w[7];
    const float* bi[7];
    const float* gg[7];
    const float* bb[7];
    for (int L = 1; L <= 6; ++L) {
        w[L]  = (const float*)d_in[1 + 4 * (L - 1) + 0];
        bi[L] = (const float*)d_in[1 + 4 * (L - 1) + 1];
        gg[L] = (const float*)d_in[1 + 4 * (L - 1) + 2];
        bb[L] = (const float*)d_in[1 + 4 * (L - 1) + 3];
    }
    const float* fcw = (const float*)d_in[25];
    const float* fcb = (const float*)d_in[26];
    float* out = (float*)d_out;

    float *c1, *h, *lg, *wp;
    cudaGetSymbolAddress((void**)&c1, g_conv1);
    cudaGetSymbolAddress((void**)&h, g_h);
    cudaGetSymbolAddress((void**)&lg, g_logits);
    cudaGetSymbolAddress((void**)&wp, g_wpack);

    repack_kernel<<<256, 256>>>(w[1], w[2], w[3], w[4], w[5], w[6], wp);
    conv1_kernel<<<dim3(64, 8), 256>>>(x, wp, bi[1], c1);
    mega_kernel<<<64, MT>>>(c1, gg[1], bb[1], wp,
                            bi[2], gg[2], bb[2],
                            bi[3], gg[3], bb[3],
                            bi[4], gg[4], bb[4],
                            bi[5], gg[5], bb[5],
                            bi[6], gg[6], bb[6],
                            h);
    fc_kernel<<<dim3(32, 16), 256>>>(h, fcw, fcb, lg);
    softmax_kernel<<<64, 256>>>(lg, out);
}

// round 8
// speedup vs baseline: 2.1423x; 1.4687x over previous
#include <cuda_runtime.h>
#include <math_constants.h>

#define BATCH 64

// scratch
__device__ float g_conv1[BATCH * 16384];
__device__ float g_out2[BATCH * 4096];
__device__ float g_out3[BATCH * 4096];
__device__ float g_h[BATCH * 256];
__device__ float g_logits[BATCH * 1024];
__device__ float g_wpack[1141760];
__device__ float2 g_part1[BATCH * 64];
__device__ float2 g_part2[BATCH * 16];
__device__ float2 g_part3[BATCH * 16];

// packed-weight offsets (floats)
#define OFF_W1 0          // 16384 pos * 52
#define OFF_W2 851968     // 4096 * 32
#define OFF_W3 983040     // 4096 * 32
#define OFF_W4 1114112    // 1024 * 12
#define OFF_W5 1126400    // 1024 * 12
#define OFF_W6 1138688    // 256 * 12

// ---------------------------------------------------------------------------
__global__ void repack_kernel(const float* __restrict__ w1, const float* __restrict__ w2,
                              const float* __restrict__ w3, const float* __restrict__ w4,
                              const float* __restrict__ w5, const float* __restrict__ w6,
                              float* __restrict__ wp) {
    int tid = blockIdx.x * blockDim.x + threadIdx.x;
    int nt = gridDim.x * blockDim.x;
    for (int i = tid; i < 16384 * 49; i += nt) { int p = i / 49, k = i - p * 49; wp[OFF_W1 + p * 52 + k] = w1[i]; }
    for (int i = tid; i < 4096 * 25; i += nt)  { int p = i / 25, k = i - p * 25; wp[OFF_W2 + p * 32 + k] = w2[i]; }
    for (int i = tid; i < 4096 * 25; i += nt)  { int p = i / 25, k = i - p * 25; wp[OFF_W3 + p * 32 + k] = w3[i]; }
    for (int i = tid; i < 1024 * 9; i += nt)   { int p = i / 9,  k = i - p * 9;  wp[OFF_W4 + p * 12 + k] = w4[i]; }
    for (int i = tid; i < 1024 * 9; i += nt)   { int p = i / 9,  k = i - p * 9;  wp[OFF_W5 + p * 12 + k] = w5[i]; }
    for (int i = tid; i < 256 * 9; i += nt)    { int p = i / 9,  k = i - p * 9;  wp[OFF_W6 + p * 12 + k] = w6[i]; }
}

// ---------------------------------------------------------------------------
// Conv1: 128x128, K=7, pad=3, + ReLU. Block = 8x32 tile x 8-batch group.
// float4 input loads (aligned halo window), weights in regs reused across 8
// batches, emits per-(sample,tile) LN1 partial sums. Grid (64,8), 256 thr.
// ---------------------------------------------------------------------------
__global__ void __launch_bounds__(256) conv1_kernel(const float* __restrict__ x,
                                                    const float* __restrict__ wp,
                                                    const float* __restrict__ b1,
                                                    float* __restrict__ out,
                                                    float2* __restrict__ part1) {
    __shared__ float sm[8][14][40];   // 8 batches x (8+6) rows x 40 cols (tj0-4 .. tj0+35)
    __shared__ float rs[8][8], rq[8][8];
    const int tile = blockIdx.x;
    const int bg = blockIdx.y;
    const int tx = tile & 3, ty = tile >> 2;
    const int tj0 = tx * 32, ti0 = ty * 8;
    const int tid = threadIdx.x;

    // load input as float4: tasks 8 batches x 14 rows x 10 f4
    for (int e = tid; e < 1120; e += 256) {
        int bb = e / 140;
        int rem = e - bb * 140;
        int r = rem / 10, k = rem - r * 10;
        int gi = ti0 - 3 + r;
        int c = tj0 - 4 + 4 * k;
        float4 v = make_float4(0.f, 0.f, 0.f, 0.f);
        if ((unsigned)gi < 128u && (unsigned)c <= 124u)
            v = *(const float4*)(x + (bg * 8 + bb) * 16384 + gi * 128 + c);
        *(float4*)(&sm[bb][r][4 * k]) = v;
    }

    const int ti = tid >> 5, tj = tid & 31;
    const int p = (ti0 + ti) * 128 + (tj0 + tj);
    float4 wreg[13];
    const float4* wv = (const float4*)(wp + OFF_W1 + p * 52);
#pragma unroll
    for (int t = 0; t < 13; ++t) wreg[t] = __ldg(wv + t);
    const float* wf = (const float*)wreg;
    const float bias = __ldg(b1 + p);
    __syncthreads();

    float r8[8];
#pragma unroll
    for (int bb = 0; bb < 8; bb += 4) {
        float a0 = bias, a1 = bias, a2 = bias, a3 = bias;
#pragma unroll
        for (int u = 0; u < 7; ++u)
#pragma unroll
            for (int v = 0; v < 7; ++v) {
                float wvv = wf[u * 7 + v];
                a0 = fmaf(sm[bb + 0][ti + u][tj + v + 1], wvv, a0);
                a1 = fmaf(sm[bb + 1][ti + u][tj + v + 1], wvv, a1);
                a2 = fmaf(sm[bb + 2][ti + u][tj + v + 1], wvv, a2);
                a3 = fmaf(sm[bb + 3][ti + u][tj + v + 1], wvv, a3);
            }
        r8[bb + 0] = fmaxf(a0, 0.0f);
        r8[bb + 1] = fmaxf(a1, 0.0f);
        r8[bb + 2] = fmaxf(a2, 0.0f);
        r8[bb + 3] = fmaxf(a3, 0.0f);
    }
#pragma unroll
    for (int bb = 0; bb < 8; ++bb)
        out[(bg * 8 + bb) * 16384 + p] = r8[bb];

    // per-sample partial sums over this tile (for LN1)
    const int wid = tid >> 5, lid = tid & 31;
#pragma unroll
    for (int s = 0; s < 8; ++s) {
        float v = r8[s], q = v * v;
#pragma unroll
        for (int o = 16; o; o >>= 1) {
            v += __shfl_down_sync(0xFFFFFFFFu, v, o);
            q += __shfl_down_sync(0xFFFFFFFFu, q, o);
        }
        if (lid == 0) { rs[wid][s] = v; rq[wid][s] = q; }
    }
    __syncthreads();
    if (tid < 8) {
        float s_ = 0.0f, q_ = 0.0f;
#pragma unroll
        for (int w = 0; w < 8; ++w) { s_ += rs[w][tid]; q_ += rq[w][tid]; }
        part1[(bg * 8 + tid) * 64 + tile] = make_float2(s_, q_);
    }
}

// ---------------------------------------------------------------------------
// conv2k: LN1(+g1,be1) + 2x2 pool applied on the fly, then conv2 (64x64, K=5)
// batch-amortized. Grid (16 tiles of 16x16, 8 groups), 256 threads.
// Emits relu(conv2) to g_out2 + per-(sample,tile) LN2 partials.
// ---------------------------------------------------------------------------
__global__ void __launch_bounds__(256) conv2k_kernel(const float* __restrict__ c1,
                                                     const float2* __restrict__ part1,
                                                     const float* __restrict__ g1,
                                                     const float* __restrict__ be1,
                                                     const float* __restrict__ wp,
                                                     const float* __restrict__ b2,
                                                     float* __restrict__ out2,
                                                     float2* __restrict__ part2) {
    __shared__ float Gs[40][40], Bs[40][40];
    __shared__ float P[8][20][24];
    __shared__ float2 stats[8];
    __shared__ float rs[8][8], rq[8][8];
    const int tile = blockIdx.x, bg = blockIdx.y;
    const int oj0 = (tile & 3) * 16, oi0 = (tile >> 2) * 16;
    const int tid = threadIdx.x, wid = tid >> 5, lid = tid & 31;

    // LN1 stats: warp w reduces sample bg*8+w over 64 tile-partials
    if (wid < 8) {
        int s = bg * 8 + wid;
        float2 a = __ldg(&part1[s * 64 + lid]);
        float2 b = __ldg(&part1[s * 64 + 32 + lid]);
        float sum = a.x + b.x, ssq = a.y + b.y;
#pragma unroll
        for (int o = 16; o; o >>= 1) {
            sum += __shfl_down_sync(0xFFFFFFFFu, sum, o);
            ssq += __shfl_down_sync(0xFFFFFFFFu, ssq, o);
        }
        if (lid == 0) {
            float mu = sum * (1.0f / 16384.0f);
            float var = ssq * (1.0f / 16384.0f) - mu * mu;
            stats[wid] = make_float2(mu, rsqrtf(var + 1e-5f));
        }
    }
    // stage g1/be1 region: rows 2*oi0-4+q (40), cols 2*oj0-4+4k (10 f4), 2 arrays
    for (int e = tid; e < 800; e += 256) {
        int arr = e / 400;
        int rem = e - arr * 400;
        int q = rem / 10, k = rem - q * 10;
        int gi = 2 * oi0 - 4 + q;
        int c = 2 * oj0 - 4 + 4 * k;
        float4 v = make_float4(0.f, 0.f, 0.f, 0.f);
        if ((unsigned)gi < 128u && (unsigned)c <= 124u)
            v = *(const float4*)((arr ? be1 : g1) + gi * 128 + c);
        if (arr) *(float4*)(&Bs[q][4 * k]) = v;
        else     *(float4*)(&Gs[q][4 * k]) = v;
    }
    __syncthreads();

    // build pooled-normalized P[8][20][20] (cols padded to 24)
    for (int e = tid; e < 1600; e += 256) {
        int sIdx = e / 200;
        int rem = e - sIdx * 200;
        int pr = rem / 10, g = rem - pr * 10;
        int pi = oi0 - 2 + pr;
        int pjA = oj0 - 2 + 2 * g;
        float pv0 = 0.0f, pv1 = 0.0f;
        if ((unsigned)pi < 64u && (unsigned)pjA < 63u) {   // pjA even, <=62
            float mu = stats[sIdx].x, rstd = stats[sIdx].y;
            int r0 = 2 * pi, c0 = 2 * pjA;
            const float* base = c1 + (bg * 8 + sIdx) * 16384;
            float4 x0 = *(const float4*)(base + r0 * 128 + c0);
            float4 x1 = *(const float4*)(base + (r0 + 1) * 128 + c0);
            int qr = 2 * pr;
            const float* G0 = &Gs[qr][4 * g];
            const float* G1 = &Gs[qr + 1][4 * g];
            const float* B0 = &Bs[qr][4 * g];
            const float* B1 = &Bs[qr + 1][4 * g];
            float n00 = (x0.x - mu) * rstd * G0[0] + B0[0];
            float n01 = (x0.y - mu) * rstd * G0[1] + B0[1];
            float n10 = (x1.x - mu) * rstd * G1[0] + B1[0];
            float n11 = (x1.y - mu) * rstd * G1[1] + B1[1];
            pv0 = fmaxf(fmaxf(n00, n01), fmaxf(n10, n11));
            float m02 = (x0.z - mu) * rstd * G0[2] + B0[2];
            float m03 = (x0.w - mu) * rstd * G0[3] + B0[3];
            float m12 = (x1.z - mu) * rstd * G1[2] + B1[2];
            float m13 = (x1.w - mu) * rstd * G1[3] + B1[3];
            pv1 = fmaxf(fmaxf(m02, m03), fmaxf(m12, m13));
        }
        P[sIdx][pr][2 * g] = pv0;
        P[sIdx][pr][2 * g + 1] = pv1;
    }
    __syncthreads();

    // conv2: thread per output position, 8 samples
    const int ti = tid >> 4, tj = tid & 15;
    const int p = (oi0 + ti) * 64 + (oj0 + tj);
    float4 wq[7];
    const float4* wvp = (const float4*)(wp + OFF_W2 + p * 32);
#pragma unroll
    for (int t = 0; t < 7; ++t) wq[t] = __ldg(wvp + t);
    const float* wf = (const float*)wq;
    const float bias = __ldg(b2 + p);

    float outv[8];
#pragma unroll
    for (int s = 0; s < 8; ++s) {
        float acc = bias;
#pragma unroll
        for (int u = 0; u < 5; ++u)
#pragma unroll
            for (int v = 0; v < 5; ++v)
                acc = fmaf(P[s][ti + u][tj + v], wf[u * 5 + v], acc);
        outv[s] = fmaxf(acc, 0.0f);
        out2[(bg * 8 + s) * 4096 + p] = outv[s];
    }
    // LN2 partials
#pragma unroll
    for (int s = 0; s < 8; ++s) {
        float v = outv[s], q = v * v;
#pragma unroll
        for (int o = 16; o; o >>= 1) {
            v += __shfl_down_sync(0xFFFFFFFFu, v, o);
            q += __shfl_down_sync(0xFFFFFFFFu, q, o);
        }
        if (lid == 0) { rs[wid][s] = v; rq[wid][s] = q; }
    }
    __syncthreads();
    if (tid < 8) {
        float s_ = 0.0f, q_ = 0.0f;
#pragma unroll
        for (int w = 0; w < 8; ++w) { s_ += rs[w][tid]; q_ += rq[w][tid]; }
        part2[(bg * 8 + tid) * 16 + tile] = make_float2(s_, q_);
    }
}

// ---------------------------------------------------------------------------
// conv3k: LN2(+g2,be2) applied on the fly, conv3 (64x64, K=5) batch-amortized.
// Grid (16,8), 256 threads. Emits relu(conv3) + LN3 partials.
// ---------------------------------------------------------------------------
__global__ void __launch_bounds__(256) conv3k_kernel(const float* __restrict__ in2,
                                                     const float2* __restrict__ part2,
                                                     const float* __restrict__ g2,
                                                     const float* __restrict__ be2,
                                                     const float* __restrict__ wp,
                                                     const float* __restrict__ b3,
                                                     float* __restrict__ out3,
                                                     float2* __restrict__ part3) {
    __shared__ float N[8][20][24];
    __shared__ float Gs2[20][24], Bs2[20][24];
    __shared__ float2 stats[8];
    __shared__ float rs[8][8], rq[8][8];
    const int tile = blockIdx.x, bg = blockIdx.y;
    const int oj0 = (tile & 3) * 16, oi0 = (tile >> 2) * 16;
    const int tid = threadIdx.x, wid = tid >> 5, lid = tid & 31;

    // LN2 stats: warp w reduces sample bg*8+w over 16 tile-partials
    if (wid < 8) {
        int s = bg * 8 + wid;
        float2 a = (lid < 16) ? __ldg(&part2[s * 16 + lid]) : make_float2(0.f, 0.f);
        float sum = a.x, ssq = a.y;
#pragma unroll
        for (int o = 16; o; o >>= 1) {
            sum += __shfl_down_sync(0xFFFFFFFFu, sum, o);
            ssq += __shfl_down_sync(0xFFFFFFFFu, ssq, o);
        }
        if (lid == 0) {
            float mu = sum * (1.0f / 4096.0f);
            float var = ssq * (1.0f / 4096.0f) - mu * mu;
            stats[wid] = make_float2(mu, rsqrtf(var + 1e-5f));
        }
    }
    // stage g2/be2 region: rows oi0-2+q (20), cols oj0-4+4k (6 f4)
    for (int e = tid; e < 240; e += 256) {
        int arr = e / 120;
        int rem = e - arr * 120;
        int q = rem / 6, k = rem - q * 6;
        int ri = oi0 - 2 + q;
        int c = oj0 - 4 + 4 * k;
        float4 v = make_float4(0.f, 0.f, 0.f, 0.f);
        if ((unsigned)ri < 64u && (unsigned)c <= 60u)
            v = *(const float4*)((arr ? be2 : g2) + ri * 64 + c);
        if (arr) *(float4*)(&Bs2[q][4 * k]) = v;
        else     *(float4*)(&Gs2[q][4 * k]) = v;
    }
    __syncthreads();

    // stage normalized input N[8][20][24]
    for (int e = tid; e < 960; e += 256) {
        int sIdx = e / 120;
        int rem = e - sIdx * 120;
        int q = rem / 6, k = rem - q * 6;
        int ri = oi0 - 2 + q;
        int c = oj0 - 4 + 4 * k;
        float4 nv = make_float4(0.f, 0.f, 0.f, 0.f);
        if ((unsigned)ri < 64u && (unsigned)c <= 60u) {
            float mu = stats[sIdx].x, rstd = stats[sIdx].y;
            float4 xv = *(const float4*)(in2 + (bg * 8 + sIdx) * 4096 + ri * 64 + c);
            const float* G = &Gs2[q][4 * k];
            const float* B = &Bs2[q][4 * k];
            nv.x = (xv.x - mu) * rstd * G[0] + B[0];
            nv.y = (xv.y - mu) * rstd * G[1] + B[1];
            nv.z = (xv.z - mu) * rstd * G[2] + B[2];
            nv.w = (xv.w - mu) * rstd * G[3] + B[3];
        }
        *(float4*)(&N[sIdx][q][4 * k]) = nv;
    }
    __syncthreads();

    // conv3
    const int ti = tid >> 4, tj = tid & 15;
    const int p = (oi0 + ti) * 64 + (oj0 + tj);
    float4 wq[7];
    const float4* wvp = (const float4*)(wp + OFF_W3 + p * 32);
#pragma unroll
    for (int t = 0; t < 7; ++t) wq[t] = __ldg(wvp + t);
    const float* wf = (const float*)wq;
    const float bias = __ldg(b3 + p);

    float outv[8];
#pragma unroll
    for (int s = 0; s < 8; ++s) {
        float acc = bias;
#pragma unroll
        for (int u = 0; u < 5; ++u)
#pragma unroll
            for (int v = 0; v < 5; ++v)
                acc = fmaf(N[s][ti + u][tj + v + 2], wf[u * 5 + v], acc);
        outv[s] = fmaxf(acc, 0.0f);
        out3[(bg * 8 + s) * 4096 + p] = outv[s];
    }
#pragma unroll
    for (int s = 0; s < 8; ++s) {
        float v = outv[s], q = v * v;
#pragma unroll
        for (int o = 16; o; o >>= 1) {
            v += __shfl_down_sync(0xFFFFFFFFu, v, o);
            q += __shfl_down_sync(0xFFFFFFFFu, q, o);
        }
        if (lid == 0) { rs[wid][s] = v; rq[wid][s] = q; }
    }
    __syncthreads();
    if (tid < 8) {
        float s_ = 0.0f, q_ = 0.0f;
#pragma unroll
        for (int w = 0; w < 8; ++w) { s_ += rs[w][tid]; q_ += rq[w][tid]; }
        part3[(bg * 8 + tid) * 16 + tile] = make_float2(s_, q_);
    }
}

// ---------------------------------------------------------------------------
// block stats over 1024 threads = 32 warps
// ---------------------------------------------------------------------------
__device__ __forceinline__ float2 bstats(float s, float ss) {
    __shared__ float r0[32], r1[32];
    int tid = threadIdx.x, wid = tid >> 5, lid = tid & 31;
#pragma unroll
    for (int o = 16; o; o >>= 1) {
        s += __shfl_down_sync(0xFFFFFFFFu, s, o);
        ss += __shfl_down_sync(0xFFFFFFFFu, ss, o);
    }
    if (lid == 0) { r0[wid] = s; r1[wid] = ss; }
    __syncthreads();
    if (wid == 0) {
        s = r0[lid];
        ss = r1[lid];
#pragma unroll
        for (int o = 16; o; o >>= 1) {
            s += __shfl_down_sync(0xFFFFFFFFu, s, o);
            ss += __shfl_down_sync(0xFFFFFFFFu, ss, o);
        }
        if (lid == 0) { r0[0] = s; r1[0] = ss; }
    }
    __syncthreads();
    float2 res = make_float2(r0[0], r1[0]);
    __syncthreads();
    return res;
}

// ---------------------------------------------------------------------------
// tail: LN3+pool -> conv4 -> LN4 -> conv5 -> LN5+pool -> conv6 -> LN6 -> h.
// Block per sample (grid=64, 1024 threads); small layers fit easily.
// ---------------------------------------------------------------------------
#define MT 1024
__global__ void __launch_bounds__(MT) tail_kernel(
    const float* __restrict__ in3, const float2* __restrict__ part3,
    const float* __restrict__ g3, const float* __restrict__ be3,
    const float* __restrict__ wp,
    const float* __restrict__ b4, const float* __restrict__ g4, const float* __restrict__ be4,
    const float* __restrict__ b5, const float* __restrict__ g5, const float* __restrict__ be5,
    const float* __restrict__ b6, const float* __restrict__ g6, const float* __restrict__ be6,
    float* __restrict__ hout) {
    __shared__ float SA[1156], SB[1156];   // 34x34 padded
    __shared__ float2 st3;
    const int tid = threadIdx.x;
    const int b = blockIdx.x;

    for (int e = tid; e < 2312; e += MT) (e < 1156 ? SA : SB - 1156)[e] = 0.0f;
    // LN3 stats from partials
    if (tid < 32) {
        float2 a = (tid < 16) ? __ldg(&part3[b * 16 + tid]) : make_float2(0.f, 0.f);
        float sum = a.x, ssq = a.y;
#pragma unroll
        for (int o = 16; o; o >>= 1) {
            sum += __shfl_down_sync(0xFFFFFFFFu, sum, o);
            ssq += __shfl_down_sync(0xFFFFFFFFu, ssq, o);
        }
        if (tid == 0) {
            float mu = sum * (1.0f / 4096.0f);
            float var = ssq * (1.0f / 4096.0f) - mu * mu;
            st3 = make_float2(mu, rsqrtf(var + 1e-5f));
        }
    }
    __syncthreads();

    // LN3 + 2x2 pool -> SB interior (34-layout). tasks: 32 rows x 16 f4-cols.
    {
        float mu = st3.x, rstd = st3.y;
        const float* base = in3 + b * 4096;
        for (int e = tid; e < 512; e += MT) {
            int pr = e >> 4, g = e & 15;
            int r0 = 2 * pr, c = 4 * g;
            float4 x0 = *(const float4*)(base + r0 * 64 + c);
            float4 x1 = *(const float4*)(base + (r0 + 1) * 64 + c);
            float4 G0 = *(const float4*)(g3 + r0 * 64 + c);
            float4 G1 = *(const float4*)(g3 + (r0 + 1) * 64 + c);
            float4 B0 = *(const float4*)(be3 + r0 * 64 + c);
            float4 B1 = *(const float4*)(be3 + (r0 + 1) * 64 + c);
            float n00 = (x0.x - mu) * rstd * G0.x + B0.x;
            float n01 = (x0.y - mu) * rstd * G0.y + B0.y;
            float n10 = (x1.x - mu) * rstd * G1.x + B1.x;
            float n11 = (x1.y - mu) * rstd * G1.y + B1.y;
            SB[(pr + 1) * 34 + 2 * g + 1] = fmaxf(fmaxf(n00, n01), fmaxf(n10, n11));
            float m02 = (x0.z - mu) * rstd * G0.z + B0.z;
            float m03 = (x0.w - mu) * rstd * G0.w + B0.w;
            float m12 = (x1.z - mu) * rstd * G1.z + B1.z;
            float m13 = (x1.w - mu) * rstd * G1.w + B1.w;
            SB[(pr + 1) * 34 + 2 * g + 2] = fmaxf(fmaxf(m02, m03), fmaxf(m12, m13));
        }
    }
    __syncthreads();

    // conv4 (32x32, K=3) SB34 -> SA34 interior, stats fused
    float s = 0.0f, ss = 0.0f;
    for (int e = tid; e < 1156; e += MT) {
        int i34 = e / 34, j34 = e - i34 * 34;
        if (i34 == 0 || i34 == 33 || j34 == 0 || j34 == 33) { SA[e] = 0.0f; continue; }
        int io = i34 - 1, jo = j34 - 1;
        int p = io * 32 + jo;
        float4 wq[3];
        const float4* wv4 = (const float4*)(wp + OFF_W4 + p * 12);
#pragma unroll
        for (int t = 0; t < 3; ++t) wq[t] = __ldg(wv4 + t);
        const float* wf = (const float*)wq;
        const float* src = SB + io * 34 + jo;
        float acc = __ldg(b4 + p);
#pragma unroll
        for (int u = 0; u < 3; ++u)
#pragma unroll
            for (int v = 0; v < 3; ++v)
                acc = fmaf(src[u * 34 + v], wf[u * 3 + v], acc);
        acc = fmaxf(acc, 0.0f);
        SA[e] = acc;
        s += acc; ss += acc * acc;
    }
    float2 st = bstats(s, ss);
    float mu = st.x * (1.0f / 1024.0f);
    float rstd = rsqrtf(st.y * (1.0f / 1024.0f) - mu * mu + 1e-5f);
    for (int p = tid; p < 1024; p += MT) {
        int idx = ((p >> 5) + 1) * 34 + (p & 31) + 1;
        SA[idx] = (SA[idx] - mu) * rstd * __ldg(g4 + p) + __ldg(be4 + p);
    }
    __syncthreads();

    // conv5 (32x32, K=3) SA34 -> SB34 interior, stats fused
    s = ss = 0.0f;
    for (int p = tid; p < 1024; p += MT) {
        int i = p >> 5, j = p & 31;
        float4 wq[3];
        const float4* wv5 = (const float4*)(wp + OFF_W5 + p * 12);
#pragma unroll
        for (int t = 0; t < 3; ++t) wq[t] = __ldg(wv5 + t);
        const float* wf = (const float*)wq;
        const float* src = SA + i * 34 + j;
        float acc = __ldg(b5 + p);
#pragma unroll
        for (int u = 0; u < 3; ++u)
#pragma unroll
            for (int v = 0; v < 3; ++v)
                acc = fmaf(src[u * 34 + v], wf[u * 3 + v], acc);
        acc = fmaxf(acc, 0.0f);
        SB[(i + 1) * 34 + j + 1] = acc;
        s += acc; ss += acc * acc;
    }
    st = bstats(s, ss);
    mu = st.x * (1.0f / 1024.0f);
    rstd = rsqrtf(st.y * (1.0f / 1024.0f) - mu * mu + 1e-5f);
    // LN5 + pool: SB34 -> SA as 18x18 padded (zero halo)
    for (int e = tid; e < 324; e += MT) {
        int i18 = e / 18, j18 = e - i18 * 18;
        if (i18 == 0 || i18 == 17 || j18 == 0 || j18 == 17) { SA[e] = 0.0f; continue; }
        int io = i18 - 1, jo = j18 - 1;
        float m = -CUDART_INF_F;
#pragma unroll
        for (int di = 0; di < 2; ++di)
#pragma unroll
            for (int dj = 0; dj < 2; ++dj) {
                int gi = 2 * io + di, gj = 2 * jo + dj;
                int q = gi * 32 + gj;
                float v = (SB[(gi + 1) * 34 + gj + 1] - mu) * rstd * __ldg(g5 + q) + __ldg(be5 + q);
                m = fmaxf(m, v);
            }
        SA[e] = m;
    }
    __syncthreads();

    // conv6 (16x16, K=3) SA18 -> SB flat [0..256), stats fused
    s = ss = 0.0f;
    for (int p = tid; p < 256; p += MT) {
        int i = p >> 4, j = p & 15;
        float4 wq[3];
        const float4* wv6 = (const float4*)(wp + OFF_W6 + p * 12);
#pragma unroll
        for (int t = 0; t < 3; ++t) wq[t] = __ldg(wv6 + t);
        const float* wf = (const float*)wq;
        const float* src = SA + i * 18 + j;
        float acc = __ldg(b6 + p);
#pragma unroll
        for (int u = 0; u < 3; ++u)
#pragma unroll
            for (int v = 0; v < 3; ++v)
                acc = fmaf(src[u * 18 + v], wf[u * 3 + v], acc);
        acc = fmaxf(acc, 0.0f);
        SB[p] = acc;
        s += acc; ss += acc * acc;
    }
    st = bstats(s, ss);
    mu = st.x * (1.0f / 256.0f);
    rstd = rsqrtf(st.y * (1.0f / 256.0f) - mu * mu + 1e-5f);
    for (int p = tid; p < 256; p += MT)
        hout[b * 256 + p] = (SB[p] - mu) * rstd * __ldg(g6 + p) + __ldg(be6 + p);
}

// ---------------------------------------------------------------------------
// FC: grid (32 col-tiles, 16 row-groups of 4 rows), 256 threads. (R7 version)
// ---------------------------------------------------------------------------
__global__ void __launch_bounds__(256) fc_kernel(const float* __restrict__ h,
                                                 const float* __restrict__ fcw,
                                                 const float* __restrict__ fcb,
                                                 float* __restrict__ logits) {
    __shared__ float hs[4 * 256];
    const int ct = blockIdx.x, rg = blockIdx.y;
    const int tid = threadIdx.x, wid = tid >> 5, lid = tid & 31;

    for (int e = tid; e < 1024; e += 256) hs[e] = h[rg * 1024 + e];
    __syncthreads();

    float hr[4][8];
#pragma unroll
    for (int r = 0; r < 4; ++r)
#pragma unroll
        for (int c = 0; c < 8; ++c) hr[r][c] = hs[r * 256 + lid * 8 + c];

    const int obase = ct * 32 + wid * 4;
#pragma unroll
    for (int t = 0; t < 4; ++t) {
        int o = obase + t;
        const float4* wr = (const float4*)(fcw + o * 256 + lid * 8);
        float4 wa = __ldg(wr), wb = __ldg(wr + 1);
        float a[4];
#pragma unroll
        for (int r = 0; r < 4; ++r) {
            a[r] = hr[r][0] * wa.x + hr[r][1] * wa.y + hr[r][2] * wa.z + hr[r][3] * wa.w
                 + hr[r][4] * wb.x + hr[r][5] * wb.y + hr[r][6] * wb.z + hr[r][7] * wb.w;
        }
#pragma unroll
        for (int r = 0; r < 4; ++r)
#pragma unroll
            for (int off = 16; off; off >>= 1) a[r] += __shfl_down_sync(0xFFFFFFFFu, a[r], off);
        if (lid == 0) {
            float bo = __ldg(fcb + o);
#pragma unroll
            for (int r = 0; r < 4; ++r) logits[(rg * 4 + r) * 1024 + o] = a[r] + bo;
        }
    }
}

// ---------------------------------------------------------------------------
__global__ void __launch_bounds__(256) softmax_kernel(const float* __restrict__ logits,
                                                      float* __restrict__ out) {
    __shared__ float red[8];
    const int b = blockIdx.x, tid = threadIdx.x, wid = tid >> 5, lid = tid & 31;
    const float* row = logits + b * 1024;

    float v[4];
#pragma unroll
    for (int t = 0; t < 4; ++t) v[t] = row[t * 256 + tid];
    float mx = fmaxf(fmaxf(v[0], v[1]), fmaxf(v[2], v[3]));
#pragma unroll
    for (int o = 16; o; o >>= 1) mx = fmaxf(mx, __shfl_xor_sync(0xFFFFFFFFu, mx, o));
    if (lid == 0) red[wid] = mx;
    __syncthreads();
    mx = red[0];
#pragma unroll
    for (int w = 1; w < 8; ++w) mx = fmaxf(mx, red[w]);
    __syncthreads();

    float e[4], ps = 0.0f;
#pragma unroll
    for (int t = 0; t < 4; ++t) { e[t] = __expf(v[t] - mx); ps += e[t]; }
#pragma unroll
    for (int o = 16; o; o >>= 1) ps += __shfl_xor_sync(0xFFFFFFFFu, ps, o);
    if (lid == 0) red[wid] = ps;
    __syncthreads();
    float tot = 0.0f;
#pragma unroll
    for (int w = 0; w < 8; ++w) tot += red[w];
    float inv = 1.0f / tot;
#pragma unroll
    for (int t = 0; t < 4; ++t) out[b * 1024 + t * 256 + tid] = e[t] * inv;
}

// ---------------------------------------------------------------------------
extern "C" void kernel_launch(void* const* d_in, const int* in_sizes, int n_in,
                              void* d_out, int out_size) {
    (void)in_sizes; (void)n_in; (void)out_size;

    const float* x = (const float*)d_in[0];
    const float* w[7];
    const float* bi[7];
    const float* gg[7];
    const float* bb[7];
    for (int L = 1; L <= 6; ++L) {
        w[L]  = (const float*)d_in[1 + 4 * (L - 1) + 0];
        bi[L] = (const float*)d_in[1 + 4 * (L - 1) + 1];
        gg[L] = (const float*)d_in[1 + 4 * (L - 1) + 2];
        bb[L] = (const float*)d_in[1 + 4 * (L - 1) + 3];
    }
    const float* fcw = (const float*)d_in[25];
    const float* fcb = (const float*)d_in[26];
    float* out = (float*)d_out;

    float *c1, *o2, *o3, *h, *lg, *wp;
    float2 *p1, *p2, *p3;
    cudaGetSymbolAddress((void**)&c1, g_conv1);
    cudaGetSymbolAddress((void**)&o2, g_out2);
    cudaGetSymbolAddress((void**)&o3, g_out3);
    cudaGetSymbolAddress((void**)&h, g_h);
    cudaGetSymbolAddress((void**)&lg, g_logits);
    cudaGetSymbolAddress((void**)&wp, g_wpack);
    cudaGetSymbolAddress((void**)&p1, g_part1);
    cudaGetSymbolAddress((void**)&p2, g_part2);
    cudaGetSymbolAddress((void**)&p3, g_part3);

    repack_kernel<<<256, 256>>>(w[1], w[2], w[3], w[4], w[5], w[6], wp);
    conv1_kernel<<<dim3(64, 8), 256>>>(x, wp, bi[1], c1, p1);
    conv2k_kernel<<<dim3(16, 8), 256>>>(c1, p1, gg[1], bb[1], wp, bi[2], o2, p2);
    conv3k_kernel<<<dim3(16, 8), 256>>>(o2, p2, gg[2], bb[2], wp, bi[3], o3, p3);
    tail_kernel<<<64, MT>>>(o3, p3, gg[3], bb[3], wp,
                            bi[4], gg[4], bb[4],
                            bi[5], gg[5], bb[5],
                            bi[6], gg[6], bb[6],
                            h);
    fc_kernel<<<dim3(32, 16), 256>>>(h, fcw, fcb, lg);
    softmax_kernel<<<64, 256>>>(lg, out);
}

// round 10
// speedup vs baseline: 2.3951x; 1.1180x over previous
#include <cuda_runtime.h>
#include <math_constants.h>

#define BATCH 64

// scratch
__device__ float g_conv1[BATCH * 16384];
__device__ float g_out2[BATCH * 4096];
__device__ float g_out3[BATCH * 4096];
__device__ float g_h[BATCH * 256];
__device__ float g_logits[BATCH * 1024];
__device__ float g_wpack[1141760];
__device__ float2 g_part1[BATCH * 64];
__device__ float2 g_part2[BATCH * 16];
__device__ float2 g_part3[BATCH * 16];

// packed-weight offsets (floats). Layout: [k-group][pos][4] so adjacent
// positions are 16B apart -> warp LDG.128 touches 4 lines, not 32.
#define OFF_W1 0          // 13 groups x 16384 x 4 = 851968
#define OFF_W2 851968     // 7 x 4096 x 4 = 114688
#define OFF_W3 966656     // 7 x 4096 x 4 = 114688
#define OFF_W4 1081344    // 3 x 1024 x 4 = 12288
#define OFF_W5 1093632    // 3 x 1024 x 4 = 12288
#define OFF_W6 1105920    // 3 x 256 x 4 = 3072

// ---------------------------------------------------------------------------
// Repack weights into k-group-major transposed layout. Padding taps (k >=
// K*K) are never written; g_wpack is zero-initialized at module load and the
// padding is never touched, so it stays zero across replays.
// ---------------------------------------------------------------------------
__global__ void repack_kernel(const float* __restrict__ w1, const float* __restrict__ w2,
                              const float* __restrict__ w3, const float* __restrict__ w4,
                              const float* __restrict__ w5, const float* __restrict__ w6,
                              float* __restrict__ wp) {
    int tid = blockIdx.x * blockDim.x + threadIdx.x;
    int nt = gridDim.x * blockDim.x;
    for (int i = tid; i < 16384 * 49; i += nt) {
        int p = i / 49, k = i - p * 49;
        wp[OFF_W1 + ((k >> 2) * 16384 + p) * 4 + (k & 3)] = w1[i];
    }
    for (int i = tid; i < 4096 * 25; i += nt) {
        int p = i / 25, k = i - p * 25;
        wp[OFF_W2 + ((k >> 2) * 4096 + p) * 4 + (k & 3)] = w2[i];
    }
    for (int i = tid; i < 4096 * 25; i += nt) {
        int p = i / 25, k = i - p * 25;
        wp[OFF_W3 + ((k >> 2) * 4096 + p) * 4 + (k & 3)] = w3[i];
    }
    for (int i = tid; i < 1024 * 9; i += nt) {
        int p = i / 9, k = i - p * 9;
        wp[OFF_W4 + ((k >> 2) * 1024 + p) * 4 + (k & 3)] = w4[i];
    }
    for (int i = tid; i < 1024 * 9; i += nt) {
        int p = i / 9, k = i - p * 9;
        wp[OFF_W5 + ((k >> 2) * 1024 + p) * 4 + (k & 3)] = w5[i];
    }
    for (int i = tid; i < 256 * 9; i += nt) {
        int p = i / 9, k = i - p * 9;
        wp[OFF_W6 + ((k >> 2) * 256 + p) * 4 + (k & 3)] = w6[i];
    }
}

// ---------------------------------------------------------------------------
// Conv1: 128x128, K=7, pad=3, + ReLU. Block = 8x32 tile x 8-batch group.
// Transposed weight loads (coalesced over positions); emits LN1 partials.
// Grid (64,8), 256 threads.
// ---------------------------------------------------------------------------
__global__ void __launch_bounds__(256) conv1_kernel(const float* __restrict__ x,
                                                    const float* __restrict__ wp,
                                                    const float* __restrict__ b1,
                                                    float* __restrict__ out,
                                                    float2* __restrict__ part1) {
    __shared__ float sm[8][14][40];   // 8 batches x (8+6) rows x 40 cols
    __shared__ float rs[8][8], rq[8][8];
    const int tile = blockIdx.x;
    const int bg = blockIdx.y;
    const int tx = tile & 3, ty = tile >> 2;
    const int tj0 = tx * 32, ti0 = ty * 8;
    const int tid = threadIdx.x;

    for (int e = tid; e < 1120; e += 256) {
        int bb = e / 140;
        int rem = e - bb * 140;
        int r = rem / 10, k = rem - r * 10;
        int gi = ti0 - 3 + r;
        int c = tj0 - 4 + 4 * k;
        float4 v = make_float4(0.f, 0.f, 0.f, 0.f);
        if ((unsigned)gi < 128u && (unsigned)c <= 124u)
            v = *(const float4*)(x + (bg * 8 + bb) * 16384 + gi * 128 + c);
        *(float4*)(&sm[bb][r][4 * k]) = v;
    }

    const int ti = tid >> 5, tj = tid & 31;
    const int p = (ti0 + ti) * 128 + (tj0 + tj);
    float4 wreg[13];
    const float4* wv = (const float4*)(wp + OFF_W1);
#pragma unroll
    for (int t = 0; t < 13; ++t) wreg[t] = __ldg(wv + t * 16384 + p);
    const float* wf = (const float*)wreg;
    const float bias = __ldg(b1 + p);
    __syncthreads();

    float r8[8];
#pragma unroll
    for (int bb = 0; bb < 8; bb += 4) {
        float a0 = bias, a1 = bias, a2 = bias, a3 = bias;
#pragma unroll
        for (int u = 0; u < 7; ++u)
#pragma unroll
            for (int v = 0; v < 7; ++v) {
                float wvv = wf[u * 7 + v];
                a0 = fmaf(sm[bb + 0][ti + u][tj + v + 1], wvv, a0);
                a1 = fmaf(sm[bb + 1][ti + u][tj + v + 1], wvv, a1);
                a2 = fmaf(sm[bb + 2][ti + u][tj + v + 1], wvv, a2);
                a3 = fmaf(sm[bb + 3][ti + u][tj + v + 1], wvv, a3);
            }
        r8[bb + 0] = fmaxf(a0, 0.0f);
        r8[bb + 1] = fmaxf(a1, 0.0f);
        r8[bb + 2] = fmaxf(a2, 0.0f);
        r8[bb + 3] = fmaxf(a3, 0.0f);
    }
#pragma unroll
    for (int bb = 0; bb < 8; ++bb)
        out[(bg * 8 + bb) * 16384 + p] = r8[bb];

    const int wid = tid >> 5, lid = tid & 31;
#pragma unroll
    for (int s = 0; s < 8; ++s) {
        float v = r8[s], q = v * v;
#pragma unroll
        for (int o = 16; o; o >>= 1) {
            v += __shfl_down_sync(0xFFFFFFFFu, v, o);
            q += __shfl_down_sync(0xFFFFFFFFu, q, o);
        }
        if (lid == 0) { rs[wid][s] = v; rq[wid][s] = q; }
    }
    __syncthreads();
    if (tid < 8) {
        float s_ = 0.0f, q_ = 0.0f;
#pragma unroll
        for (int w = 0; w < 8; ++w) { s_ += rs[w][tid]; q_ += rq[w][tid]; }
        part1[(bg * 8 + tid) * 64 + tile] = make_float2(s_, q_);
    }
}

// ---------------------------------------------------------------------------
// conv2k: LN1(+g1,be1) + 2x2 pool on the fly, then conv2 (64x64, K=5)
// batch-amortized. Grid (16 tiles of 16x16, 8 groups), 256 threads.
// ---------------------------------------------------------------------------
__global__ void __launch_bounds__(256) conv2k_kernel(const float* __restrict__ c1,
                                                     const float2* __restrict__ part1,
                                                     const float* __restrict__ g1,
                                                     const float* __restrict__ be1,
                                                     const float* __restrict__ wp,
                                                     const float* __restrict__ b2,
                                                     float* __restrict__ out2,
                                                     float2* __restrict__ part2) {
    __shared__ float Gs[40][40], Bs[40][40];
    __shared__ float P[8][20][24];
    __shared__ float2 stats[8];
    __shared__ float rs[8][8], rq[8][8];
    const int tile = blockIdx.x, bg = blockIdx.y;
    const int oj0 = (tile & 3) * 16, oi0 = (tile >> 2) * 16;
    const int tid = threadIdx.x, wid = tid >> 5, lid = tid & 31;

    if (wid < 8) {
        int s = bg * 8 + wid;
        float2 a = __ldg(&part1[s * 64 + lid]);
        float2 b = __ldg(&part1[s * 64 + 32 + lid]);
        float sum = a.x + b.x, ssq = a.y + b.y;
#pragma unroll
        for (int o = 16; o; o >>= 1) {
            sum += __shfl_down_sync(0xFFFFFFFFu, sum, o);
            ssq += __shfl_down_sync(0xFFFFFFFFu, ssq, o);
        }
        if (lid == 0) {
            float mu = sum * (1.0f / 16384.0f);
            float var = ssq * (1.0f / 16384.0f) - mu * mu;
            stats[wid] = make_float2(mu, rsqrtf(var + 1e-5f));
        }
    }
    for (int e = tid; e < 800; e += 256) {
        int arr = e / 400;
        int rem = e - arr * 400;
        int q = rem / 10, k = rem - q * 10;
        int gi = 2 * oi0 - 4 + q;
        int c = 2 * oj0 - 4 + 4 * k;
        float4 v = make_float4(0.f, 0.f, 0.f, 0.f);
        if ((unsigned)gi < 128u && (unsigned)c <= 124u)
            v = *(const float4*)((arr ? be1 : g1) + gi * 128 + c);
        if (arr) *(float4*)(&Bs[q][4 * k]) = v;
        else     *(float4*)(&Gs[q][4 * k]) = v;
    }
    __syncthreads();

    for (int e = tid; e < 1600; e += 256) {
        int sIdx = e / 200;
        int rem = e - sIdx * 200;
        int pr = rem / 10, g = rem - pr * 10;
        int pi = oi0 - 2 + pr;
        int pjA = oj0 - 2 + 2 * g;
        float pv0 = 0.0f, pv1 = 0.0f;
        if ((unsigned)pi < 64u && (unsigned)pjA < 63u) {
            float mu = stats[sIdx].x, rstd = stats[sIdx].y;
            int r0 = 2 * pi, c0 = 2 * pjA;
            const float* base = c1 + (bg * 8 + sIdx) * 16384;
            float4 x0 = *(const float4*)(base + r0 * 128 + c0);
            float4 x1 = *(const float4*)(base + (r0 + 1) * 128 + c0);
            int qr = 2 * pr;
            const float* G0 = &Gs[qr][4 * g];
            const float* G1 = &Gs[qr + 1][4 * g];
            const float* B0 = &Bs[qr][4 * g];
            const float* B1 = &Bs[qr + 1][4 * g];
            float n00 = (x0.x - mu) * rstd * G0[0] + B0[0];
            float n01 = (x0.y - mu) * rstd * G0[1] + B0[1];
            float n10 = (x1.x - mu) * rstd * G1[0] + B1[0];
            float n11 = (x1.y - mu) * rstd * G1[1] + B1[1];
            pv0 = fmaxf(fmaxf(n00, n01), fmaxf(n10, n11));
            float m02 = (x0.z - mu) * rstd * G0[2] + B0[2];
            float m03 = (x0.w - mu) * rstd * G0[3] + B0[3];
            float m12 = (x1.z - mu) * rstd * G1[2] + B1[2];
            float m13 = (x1.w - mu) * rstd * G1[3] + B1[3];
            pv1 = fmaxf(fmaxf(m02, m03), fmaxf(m12, m13));
        }
        P[sIdx][pr][2 * g] = pv0;
        P[sIdx][pr][2 * g + 1] = pv1;
    }
    __syncthreads();

    const int ti = tid >> 4, tj = tid & 15;
    const int p = (oi0 + ti) * 64 + (oj0 + tj);
    float4 wq[7];
    const float4* wvp = (const float4*)(wp + OFF_W2);
#pragma unroll
    for (int t = 0; t < 7; ++t) wq[t] = __ldg(wvp + t * 4096 + p);
    const float* wf = (const float*)wq;
    const float bias = __ldg(b2 + p);

    float outv[8];
#pragma unroll
    for (int s = 0; s < 8; ++s) {
        float acc = bias;
#pragma unroll
        for (int u = 0; u < 5; ++u)
#pragma unroll
            for (int v = 0; v < 5; ++v)
                acc = fmaf(P[s][ti + u][tj + v], wf[u * 5 + v], acc);
        outv[s] = fmaxf(acc, 0.0f);
        out2[(bg * 8 + s) * 4096 + p] = outv[s];
    }
#pragma unroll
    for (int s = 0; s < 8; ++s) {
        float v = outv[s], q = v * v;
#pragma unroll
        for (int o = 16; o; o >>= 1) {
            v += __shfl_down_sync(0xFFFFFFFFu, v, o);
            q += __shfl_down_sync(0xFFFFFFFFu, q, o);
        }
        if (lid == 0) { rs[wid][s] = v; rq[wid][s] = q; }
    }
    __syncthreads();
    if (tid < 8) {
        float s_ = 0.0f, q_ = 0.0f;
#pragma unroll
        for (int w = 0; w < 8; ++w) { s_ += rs[w][tid]; q_ += rq[w][tid]; }
        part2[(bg * 8 + tid) * 16 + tile] = make_float2(s_, q_);
    }
}

// ---------------------------------------------------------------------------
// conv3k: LN2(+g2,be2) on the fly, conv3 (64x64, K=5) batch-amortized.
// Grid (16,8), 256 threads.
// ---------------------------------------------------------------------------
__global__ void __launch_bounds__(256) conv3k_kernel(const float* __restrict__ in2,
                                                     const float2* __restrict__ part2,
                                                     const float* __restrict__ g2,
                                                     const float* __restrict__ be2,
                                                     const float* __restrict__ wp,
                                                     const float* __restrict__ b3,
                                                     float* __restrict__ out3,
                                                     float2* __restrict__ part3) {
    __shared__ float N[8][20][24];
    __shared__ float Gs2[20][24], Bs2[20][24];
    __shared__ float2 stats[8];
    __shared__ float rs[8][8], rq[8][8];
    const int tile = blockIdx.x, bg = blockIdx.y;
    const int oj0 = (tile & 3) * 16, oi0 = (tile >> 2) * 16;
    const int tid = threadIdx.x, wid = tid >> 5, lid = tid & 31;

    if (wid < 8) {
        int s = bg * 8 + wid;
        float2 a = (lid < 16) ? __ldg(&part2[s * 16 + lid]) : make_float2(0.f, 0.f);
        float sum = a.x, ssq = a.y;
#pragma unroll
        for (int o = 16; o; o >>= 1) {
            sum += __shfl_down_sync(0xFFFFFFFFu, sum, o);
            ssq += __shfl_down_sync(0xFFFFFFFFu, ssq, o);
        }
        if (lid == 0) {
            float mu = sum * (1.0f / 4096.0f);
            float var = ssq * (1.0f / 4096.0f) - mu * mu;
            stats[wid] = make_float2(mu, rsqrtf(var + 1e-5f));
        }
    }
    for (int e = tid; e < 240; e += 256) {
        int arr = e / 120;
        int rem = e - arr * 120;
        int q = rem / 6, k = rem - q * 6;
        int ri = oi0 - 2 + q;
        int c = oj0 - 4 + 4 * k;
        float4 v = make_float4(0.f, 0.f, 0.f, 0.f);
        if ((unsigned)ri < 64u && (unsigned)c <= 60u)
            v = *(const float4*)((arr ? be2 : g2) + ri * 64 + c);
        if (arr) *(float4*)(&Bs2[q][4 * k]) = v;
        else     *(float4*)(&Gs2[q][4 * k]) = v;
    }
    __syncthreads();

    for (int e = tid; e < 960; e += 256) {
        int sIdx = e / 120;
        int rem = e - sIdx * 120;
        int q = rem / 6, k = rem - q * 6;
        int ri = oi0 - 2 + q;
        int c = oj0 - 4 + 4 * k;
        float4 nv = make_float4(0.f, 0.f, 0.f, 0.f);
        if ((unsigned)ri < 64u && (unsigned)c <= 60u) {
            float mu = stats[sIdx].x, rstd = stats[sIdx].y;
            float4 xv = *(const float4*)(in2 + (bg * 8 + sIdx) * 4096 + ri * 64 + c);
            const float* G = &Gs2[q][4 * k];
            const float* B = &Bs2[q][4 * k];
            nv.x = (xv.x - mu) * rstd * G[0] + B[0];
            nv.y = (xv.y - mu) * rstd * G[1] + B[1];
            nv.z = (xv.z - mu) * rstd * G[2] + B[2];
            nv.w = (xv.w - mu) * rstd * G[3] + B[3];
        }
        *(float4*)(&N[sIdx][q][4 * k]) = nv;
    }
    __syncthreads();

    const int ti = tid >> 4, tj = tid & 15;
    const int p = (oi0 + ti) * 64 + (oj0 + tj);
    float4 wq[7];
    const float4* wvp = (const float4*)(wp + OFF_W3);
#pragma unroll
    for (int t = 0; t < 7; ++t) wq[t] = __ldg(wvp + t * 4096 + p);
    const float* wf = (const float*)wq;
    const float bias = __ldg(b3 + p);

    float outv[8];
#pragma unroll
    for (int s = 0; s < 8; ++s) {
        float acc = bias;
#pragma unroll
        for (int u = 0; u < 5; ++u)
#pragma unroll
            for (int v = 0; v < 5; ++v)
                acc = fmaf(N[s][ti + u][tj + v + 2], wf[u * 5 + v], acc);
        outv[s] = fmaxf(acc, 0.0f);
        out3[(bg * 8 + s) * 4096 + p] = outv[s];
    }
#pragma unroll
    for (int s = 0; s < 8; ++s) {
        float v = outv[s], q = v * v;
#pragma unroll
        for (int o = 16; o; o >>= 1) {
            v += __shfl_down_sync(0xFFFFFFFFu, v, o);
            q += __shfl_down_sync(0xFFFFFFFFu, q, o);
        }
        if (lid == 0) { rs[wid][s] = v; rq[wid][s] = q; }
    }
    __syncthreads();
    if (tid < 8) {
        float s_ = 0.0f, q_ = 0.0f;
#pragma unroll
        for (int w = 0; w < 8; ++w) { s_ += rs[w][tid]; q_ += rq[w][tid]; }
        part3[(bg * 8 + tid) * 16 + tile] = make_float2(s_, q_);
    }
}

// ---------------------------------------------------------------------------
__device__ __forceinline__ float2 bstats(float s, float ss) {
    __shared__ float r0[32], r1[32];
    int tid = threadIdx.x, wid = tid >> 5, lid = tid & 31;
#pragma unroll
    for (int o = 16; o; o >>= 1) {
        s += __shfl_down_sync(0xFFFFFFFFu, s, o);
        ss += __shfl_down_sync(0xFFFFFFFFu, ss, o);
    }
    if (lid == 0) { r0[wid] = s; r1[wid] = ss; }
    __syncthreads();
    if (wid == 0) {
        s = r0[lid];
        ss = r1[lid];
#pragma unroll
        for (int o = 16; o; o >>= 1) {
            s += __shfl_down_sync(0xFFFFFFFFu, s, o);
            ss += __shfl_down_sync(0xFFFFFFFFu, ss, o);
        }
        if (lid == 0) { r0[0] = s; r1[0] = ss; }
    }
    __syncthreads();
    float2 res = make_float2(r0[0], r1[0]);
    __syncthreads();
    return res;
}

// ---------------------------------------------------------------------------
// tail: LN3+pool -> conv4 -> LN4 -> conv5 -> LN5+pool -> conv6 -> LN6 -> h.
// Block per sample (grid=64, 1024 threads).
// ---------------------------------------------------------------------------
#define MT 1024
__global__ void __launch_bounds__(MT) tail_kernel(
    const float* __restrict__ in3, const float2* __restrict__ part3,
    const float* __restrict__ g3, const float* __restrict__ be3,
    const float* __restrict__ wp,
    const float* __restrict__ b4, const float* __restrict__ g4, const float* __restrict__ be4,
    const float* __restrict__ b5, const float* __restrict__ g5, const float* __restrict__ be5,
    const float* __restrict__ b6, const float* __restrict__ g6, const float* __restrict__ be6,
    float* __restrict__ hout) {
    __shared__ float SA[1156], SB[1156];   // 34x34 padded
    __shared__ float2 st3;
    const int tid = threadIdx.x;
    const int b = blockIdx.x;

    for (int e = tid; e < 2312; e += MT) (e < 1156 ? SA : SB - 1156)[e] = 0.0f;
    if (tid < 32) {
        float2 a = (tid < 16) ? __ldg(&part3[b * 16 + tid]) : make_float2(0.f, 0.f);
        float sum = a.x, ssq = a.y;
#pragma unroll
        for (int o = 16; o; o >>= 1) {
            sum += __shfl_down_sync(0xFFFFFFFFu, sum, o);
            ssq += __shfl_down_sync(0xFFFFFFFFu, ssq, o);
        }
        if (tid == 0) {
            float mu = sum * (1.0f / 4096.0f);
            float var = ssq * (1.0f / 4096.0f) - mu * mu;
            st3 = make_float2(mu, rsqrtf(var + 1e-5f));
        }
    }
    __syncthreads();

    {
        float mu = st3.x, rstd = st3.y;
        const float* base = in3 + b * 4096;
        for (int e = tid; e < 512; e += MT) {
            int pr = e >> 4, g = e & 15;
            int r0 = 2 * pr, c = 4 * g;
            float4 x0 = *(const float4*)(base + r0 * 64 + c);
            float4 x1 = *(const float4*)(base + (r0 + 1) * 64 + c);
            float4 G0 = *(const float4*)(g3 + r0 * 64 + c);
            float4 G1 = *(const float4*)(g3 + (r0 + 1) * 64 + c);
            float4 B0 = *(const float4*)(be3 + r0 * 64 + c);
            float4 B1 = *(const float4*)(be3 + (r0 + 1) * 64 + c);
            float n00 = (x0.x - mu) * rstd * G0.x + B0.x;
            float n01 = (x0.y - mu) * rstd * G0.y + B0.y;
            float n10 = (x1.x - mu) * rstd * G1.x + B1.x;
            float n11 = (x1.y - mu) * rstd * G1.y + B1.y;
            SB[(pr + 1) * 34 + 2 * g + 1] = fmaxf(fmaxf(n00, n01), fmaxf(n10, n11));
            float m02 = (x0.z - mu) * rstd * G0.z + B0.z;
            float m03 = (x0.w - mu) * rstd * G0.w + B0.w;
            float m12 = (x1.z - mu) * rstd * G1.z + B1.z;
            float m13 = (x1.w - mu) * rstd * G1.w + B1.w;
            SB[(pr + 1) * 34 + 2 * g + 2] = fmaxf(fmaxf(m02, m03), fmaxf(m12, m13));
        }
    }
    __syncthreads();

    // conv4 (32x32, K=3) SB34 -> SA34 interior, stats fused
    float s = 0.0f, ss = 0.0f;
    for (int e = tid; e < 1156; e += MT) {
        int i34 = e / 34, j34 = e - i34 * 34;
        if (i34 == 0 || i34 == 33 || j34 == 0 || j34 == 33) { SA[e] = 0.0f; continue; }
        int io = i34 - 1, jo = j34 - 1;
        int p = io * 32 + jo;
        float4 wq[3];
        const float4* wv4 = (const float4*)(wp + OFF_W4);
#pragma unroll
        for (int t = 0; t < 3; ++t) wq[t] = __ldg(wv4 + t * 1024 + p);
        const float* wf = (const float*)wq;
        const float* src = SB + io * 34 + jo;
        float acc = __ldg(b4 + p);
#pragma unroll
        for (int u = 0; u < 3; ++u)
#pragma unroll
            for (int v = 0; v < 3; ++v)
                acc = fmaf(src[u * 34 + v], wf[u * 3 + v], acc);
        acc = fmaxf(acc, 0.0f);
        SA[e] = acc;
        s += acc; ss += acc * acc;
    }
    float2 st = bstats(s, ss);
    float mu = st.x * (1.0f / 1024.0f);
    float rstd = rsqrtf(st.y * (1.0f / 1024.0f) - mu * mu + 1e-5f);
    for (int p = tid; p < 1024; p += MT) {
        int idx = ((p >> 5) + 1) * 34 + (p & 31) + 1;
        SA[idx] = (SA[idx] - mu) * rstd * __ldg(g4 + p) + __ldg(be4 + p);
    }
    __syncthreads();

    // conv5 (32x32, K=3) SA34 -> SB34 interior, stats fused
    s = ss = 0.0f;
    for (int p = tid; p < 1024; p += MT) {
        int i = p >> 5, j = p & 31;
        float4 wq[3];
        const float4* wv5 = (const float4*)(wp + OFF_W5);
#pragma unroll
        for (int t = 0; t < 3; ++t) wq[t] = __ldg(wv5 + t * 1024 + p);
        const float* wf = (const float*)wq;
        const float* src = SA + i * 34 + j;
        float acc = __ldg(b5 + p);
#pragma unroll
        for (int u = 0; u < 3; ++u)
#pragma unroll
            for (int v = 0; v < 3; ++v)
                acc = fmaf(src[u * 34 + v], wf[u * 3 + v], acc);
        acc = fmaxf(acc, 0.0f);
        SB[(i + 1) * 34 + j + 1] = acc;
        s += acc; ss += acc * acc;
    }
    st = bstats(s, ss);
    mu = st.x * (1.0f / 1024.0f);
    rstd = rsqrtf(st.y * (1.0f / 1024.0f) - mu * mu + 1e-5f);
    // LN5 + pool: SB34 -> SA as 18x18 padded (zero halo)
    for (int e = tid; e < 324; e += MT) {
        int i18 = e / 18, j18 = e - i18 * 18;
        if (i18 == 0 || i18 == 17 || j18 == 0 || j18 == 17) { SA[e] = 0.0f; continue; }
        int io = i18 - 1, jo = j18 - 1;
        float m = -CUDART_INF_F;
#pragma unroll
        for (int di = 0; di < 2; ++di)
#pragma unroll
            for (int dj = 0; dj < 2; ++dj) {
                int gi = 2 * io + di, gj = 2 * jo + dj;
                int q = gi * 32 + gj;
                float v = (SB[(gi + 1) * 34 + gj + 1] - mu) * rstd * __ldg(g5 + q) + __ldg(be5 + q);
                m = fmaxf(m, v);
            }
        SA[e] = m;
    }
    __syncthreads();

    // conv6 (16x16, K=3) SA18 -> SB flat, stats fused
    s = ss = 0.0f;
    for (int p = tid; p < 256; p += MT) {
        int i = p >> 4, j = p & 15;
        float4 wq[3];
        const float4* wv6 = (const float4*)(wp + OFF_W6);
#pragma unroll
        for (int t = 0; t < 3; ++t) wq[t] = __ldg(wv6 + t * 256 + p);
        const float* wf = (const float*)wq;
        const float* src = SA + i * 18 + j;
        float acc = __ldg(b6 + p);
#pragma unroll
        for (int u = 0; u < 3; ++u)
#pragma unroll
            for (int v = 0; v < 3; ++v)
                acc = fmaf(src[u * 18 + v], wf[u * 3 + v], acc);
        acc = fmaxf(acc, 0.0f);
        SB[p] = acc;
        s += acc; ss += acc * acc;
    }
    st = bstats(s, ss);
    mu = st.x * (1.0f / 256.0f);
    rstd = rsqrtf(st.y * (1.0f / 256.0f) - mu * mu + 1e-5f);
    for (int p = tid; p < 256; p += MT)
        hout[b * 256 + p] = (SB[p] - mu) * rstd * __ldg(g6 + p) + __ldg(be6 + p);
}

// ---------------------------------------------------------------------------
// FC: grid (32 col-tiles, 16 row-groups of 4 rows), 256 threads.
// ---------------------------------------------------------------------------
__global__ void __launch_bounds__(256) fc_kernel(const float* __restrict__ h,
                                                 const float* __restrict__ fcw,
                                                 const float* __restrict__ fcb,
                                                 float* __restrict__ logits) {
    __shared__ float hs[4 * 256];
    const int ct = blockIdx.x, rg = blockIdx.y;
    const int tid = threadIdx.x, wid = tid >> 5, lid = tid & 31;

    for (int e = tid; e < 1024; e += 256) hs[e] = h[rg * 1024 + e];
    __syncthreads();

    float hr[4][8];
#pragma unroll
    for (int r = 0; r < 4; ++r)
#pragma unroll
        for (int c = 0; c < 8; ++c) hr[r][c] = hs[r * 256 + lid * 8 + c];

    const int obase = ct * 32 + wid * 4;
#pragma unroll
    for (int t = 0; t < 4; ++t) {
        int o = obase + t;
        const float4* wr = (const float4*)(fcw + o * 256 + lid * 8);
        float4 wa = __ldg(wr), wb = __ldg(wr + 1);
        float a[4];
#pragma unroll
        for (int r = 0; r < 4; ++r) {
            a[r] = hr[r][0] * wa.x + hr[r][1] * wa.y + hr[r][2] * wa.z + hr[r][3] * wa.w
                 + hr[r][4] * wb.x + hr[r][5] * wb.y + hr[r][6] * wb.z + hr[r][7] * wb.w;
        }
#pragma unroll
        for (int r = 0; r < 4; ++r)
#pragma unroll
            for (int off = 16; off; off >>= 1) a[r] += __shfl_down_sync(0xFFFFFFFFu, a[r], off);
        if (lid == 0) {
            float bo = __ldg(fcb + o);
#pragma unroll
            for (int r = 0; r < 4; ++r) logits[(rg * 4 + r) * 1024 + o] = a[r] + bo;
        }
    }
}

// ---------------------------------------------------------------------------
__global__ void __launch_bounds__(256) softmax_kernel(const float* __restrict__ logits,
                                                      float* __restrict__ out) {
    __shared__ float red[8];
    const int b = blockIdx.x, tid = threadIdx.x, wid = tid >> 5, lid = tid & 31;
    const float* row = logits + b * 1024;

    float v[4];
#pragma unroll
    for (int t = 0; t < 4; ++t) v[t] = row[t * 256 + tid];
    float mx = fmaxf(fmaxf(v[0], v[1]), fmaxf(v[2], v[3]));
#pragma unroll
    for (int o = 16; o; o >>= 1) mx = fmaxf(mx, __shfl_xor_sync(0xFFFFFFFFu, mx, o));
    if (lid == 0) red[wid] = mx;
    __syncthreads();
    mx = red[0];
#pragma unroll
    for (int w = 1; w < 8; ++w) mx = fmaxf(mx, red[w]);
    __syncthreads();

    float e[4], ps = 0.0f;
#pragma unroll
    for (int t = 0; t < 4; ++t) { e[t] = __expf(v[t] - mx); ps += e[t]; }
#pragma unroll
    for (int o = 16; o; o >>= 1) ps += __shfl_xor_sync(0xFFFFFFFFu, ps, o);
    if (lid == 0) red[wid] = ps;
    __syncthreads();
    float tot = 0.0f;
#pragma unroll
    for (int w = 0; w < 8; ++w) tot += red[w];
    float inv = 1.0f / tot;
#pragma unroll
    for (int t = 0; t < 4; ++t) out[b * 1024 + t * 256 + tid] = e[t] * inv;
}

// ---------------------------------------------------------------------------
extern "C" void kernel_launch(void* const* d_in, const int* in_sizes, int n_in,
                              void* d_out, int out_size) {
    (void)in_sizes; (void)n_in; (void)out_size;

    const float* x = (const float*)d_in[0];
    const float* w[7];
    const float* bi[7];
    const float* gg[7];
    const float* bb[7];
    for (int L = 1; L <= 6; ++L) {
        w[L]  = (const float*)d_in[1 + 4 * (L - 1) + 0];
        bi[L] = (const float*)d_in[1 + 4 * (L - 1) + 1];
        gg[L] = (const float*)d_in[1 + 4 * (L - 1) + 2];
        bb[L] = (const float*)d_in[1 + 4 * (L - 1) + 3];
    }
    const float* fcw = (const float*)d_in[25];
    const float* fcb = (const float*)d_in[26];
    float* out = (float*)d_out;

    float *c1, *o2, *o3, *h, *lg, *wp;
    float2 *p1, *p2, *p3;
    cudaGetSymbolAddress((void**)&c1, g_conv1);
    cudaGetSymbolAddress((void**)&o2, g_out2);
    cudaGetSymbolAddress((void**)&o3, g_out3);
    cudaGetSymbolAddress((void**)&h, g_h);
    cudaGetSymbolAddress((void**)&lg, g_logits);
    cudaGetSymbolAddress((void**)&wp, g_wpack);
    cudaGetSymbolAddress((void**)&p1, g_part1);
    cudaGetSymbolAddress((void**)&p2, g_part2);
    cudaGetSymbolAddress((void**)&p3, g_part3);

    repack_kernel<<<256, 256>>>(w[1], w[2], w[3], w[4], w[5], w[6], wp);
    conv1_kernel<<<dim3(64, 8), 256>>>(x, wp, bi[1], c1, p1);
    conv2k_kernel<<<dim3(16, 8), 256>>>(c1, p1, gg[1], bb[1], wp, bi[2], o2, p2);
    conv3k_kernel<<<dim3(16, 8), 256>>>(o2, p2, gg[2], bb[2], wp, bi[3], o3, p3);
    tail_kernel<<<64, MT>>>(o3, p3, gg[3], bb[3], wp,
                            bi[4], gg[4], bb[4],
                            bi[5], gg[5], bb[5],
                            bi[6], gg[6], bb[6],
                            h);
    fc_kernel<<<dim3(32, 16), 256>>>(h, fcw, fcb, lg);
    softmax_kernel<<<64, 256>>>(lg, out);
}

// round 11
// speedup vs baseline: 2.4357x; 1.0170x over previous
#include <cuda_runtime.h>
#include <math_constants.h>

#define BATCH 64

// scratch
__device__ float g_conv1[BATCH * 16384];
__device__ float g_out2[BATCH * 4096];
__device__ float g_out3[BATCH * 4096];
__device__ float g_h[BATCH * 256];
__device__ float g_logits[BATCH * 1024];
__device__ float g_wpack[1141760];
__device__ float2 g_part1[BATCH * 64];
__device__ float2 g_part2[BATCH * 16];
__device__ float2 g_part3[BATCH * 16];

// packed-weight offsets (floats). Layout: [k-group][pos][4] so adjacent
// positions are 16B apart -> warp LDG.128 touches 4 lines, not 32.
#define OFF_W1 0          // 13 groups x 16384 x 4 = 851968
#define OFF_W2 851968     // 7 x 4096 x 4 = 114688
#define OFF_W3 966656     // 7 x 4096 x 4 = 114688
#define OFF_W4 1081344    // 3 x 1024 x 4 = 12288
#define OFF_W5 1093632    // 3 x 1024 x 4 = 12288
#define OFF_W6 1105920    // 3 x 256 x 4 = 3072

// ---------------------------------------------------------------------------
__global__ void repack_kernel(const float* __restrict__ w1, const float* __restrict__ w2,
                              const float* __restrict__ w3, const float* __restrict__ w4,
                              const float* __restrict__ w5, const float* __restrict__ w6,
                              float* __restrict__ wp) {
    int tid = blockIdx.x * blockDim.x + threadIdx.x;
    int nt = gridDim.x * blockDim.x;
    for (int i = tid; i < 16384 * 49; i += nt) {
        int p = i / 49, k = i - p * 49;
        wp[OFF_W1 + ((k >> 2) * 16384 + p) * 4 + (k & 3)] = w1[i];
    }
    for (int i = tid; i < 4096 * 25; i += nt) {
        int p = i / 25, k = i - p * 25;
        wp[OFF_W2 + ((k >> 2) * 4096 + p) * 4 + (k & 3)] = w2[i];
    }
    for (int i = tid; i < 4096 * 25; i += nt) {
        int p = i / 25, k = i - p * 25;
        wp[OFF_W3 + ((k >> 2) * 4096 + p) * 4 + (k & 3)] = w3[i];
    }
    for (int i = tid; i < 1024 * 9; i += nt) {
        int p = i / 9, k = i - p * 9;
        wp[OFF_W4 + ((k >> 2) * 1024 + p) * 4 + (k & 3)] = w4[i];
    }
    for (int i = tid; i < 1024 * 9; i += nt) {
        int p = i / 9, k = i - p * 9;
        wp[OFF_W5 + ((k >> 2) * 1024 + p) * 4 + (k & 3)] = w5[i];
    }
    for (int i = tid; i < 256 * 9; i += nt) {
        int p = i / 9, k = i - p * 9;
        wp[OFF_W6 + ((k >> 2) * 256 + p) * 4 + (k & 3)] = w6[i];
    }
}

// ---------------------------------------------------------------------------
// Conv1: 128x128, K=7, pad=3, + ReLU. Block = 8x32 tile x 8-batch group.
// Grid (64,8), 256 threads.
// ---------------------------------------------------------------------------
__global__ void __launch_bounds__(256) conv1_kernel(const float* __restrict__ x,
                                                    const float* __restrict__ wp,
                                                    const float* __restrict__ b1,
                                                    float* __restrict__ out,
                                                    float2* __restrict__ part1) {
    __shared__ float sm[8][14][40];
    __shared__ float rs[8][8], rq[8][8];
    const int tile = blockIdx.x;
    const int bg = blockIdx.y;
    const int tx = tile & 3, ty = tile >> 2;
    const int tj0 = tx * 32, ti0 = ty * 8;
    const int tid = threadIdx.x;

    for (int e = tid; e < 1120; e += 256) {
        int bb = e / 140;
        int rem = e - bb * 140;
        int r = rem / 10, k = rem - r * 10;
        int gi = ti0 - 3 + r;
        int c = tj0 - 4 + 4 * k;
        float4 v = make_float4(0.f, 0.f, 0.f, 0.f);
        if ((unsigned)gi < 128u && (unsigned)c <= 124u)
            v = *(const float4*)(x + (bg * 8 + bb) * 16384 + gi * 128 + c);
        *(float4*)(&sm[bb][r][4 * k]) = v;
    }

    const int ti = tid >> 5, tj = tid & 31;
    const int p = (ti0 + ti) * 128 + (tj0 + tj);
    float4 wreg[13];
    const float4* wv = (const float4*)(wp + OFF_W1);
#pragma unroll
    for (int t = 0; t < 13; ++t) wreg[t] = __ldg(wv + t * 16384 + p);
    const float* wf = (const float*)wreg;
    const float bias = __ldg(b1 + p);
    __syncthreads();

    float r8[8];
#pragma unroll
    for (int bb = 0; bb < 8; bb += 4) {
        float a0 = bias, a1 = bias, a2 = bias, a3 = bias;
#pragma unroll
        for (int u = 0; u < 7; ++u)
#pragma unroll
            for (int v = 0; v < 7; ++v) {
                float wvv = wf[u * 7 + v];
                a0 = fmaf(sm[bb + 0][ti + u][tj + v + 1], wvv, a0);
                a1 = fmaf(sm[bb + 1][ti + u][tj + v + 1], wvv, a1);
                a2 = fmaf(sm[bb + 2][ti + u][tj + v + 1], wvv, a2);
                a3 = fmaf(sm[bb + 3][ti + u][tj + v + 1], wvv, a3);
            }
        r8[bb + 0] = fmaxf(a0, 0.0f);
        r8[bb + 1] = fmaxf(a1, 0.0f);
        r8[bb + 2] = fmaxf(a2, 0.0f);
        r8[bb + 3] = fmaxf(a3, 0.0f);
    }
#pragma unroll
    for (int bb = 0; bb < 8; ++bb)
        out[(bg * 8 + bb) * 16384 + p] = r8[bb];

    const int wid = tid >> 5, lid = tid & 31;
#pragma unroll
    for (int s = 0; s < 8; ++s) {
        float v = r8[s], q = v * v;
#pragma unroll
        for (int o = 16; o; o >>= 1) {
            v += __shfl_down_sync(0xFFFFFFFFu, v, o);
            q += __shfl_down_sync(0xFFFFFFFFu, q, o);
        }
        if (lid == 0) { rs[wid][s] = v; rq[wid][s] = q; }
    }
    __syncthreads();
    if (tid < 8) {
        float s_ = 0.0f, q_ = 0.0f;
#pragma unroll
        for (int w = 0; w < 8; ++w) { s_ += rs[w][tid]; q_ += rq[w][tid]; }
        part1[(bg * 8 + tid) * 64 + tile] = make_float2(s_, q_);
    }
}

// ---------------------------------------------------------------------------
// conv2k: LN1(+g1,be1) + 2x2 pool on the fly, then conv2 (64x64, K=5)
// batch-amortized. Grid (16 tiles of 16x16, 8 groups), 512 threads:
// (256 positions) x (2 sample-halves), 4 samples per thread.
// ---------------------------------------------------------------------------
__global__ void __launch_bounds__(512) conv2k_kernel(const float* __restrict__ c1,
                                                     const float2* __restrict__ part1,
                                                     const float* __restrict__ g1,
                                                     const float* __restrict__ be1,
                                                     const float* __restrict__ wp,
                                                     const float* __restrict__ b2,
                                                     float* __restrict__ out2,
                                                     float2* __restrict__ part2) {
    __shared__ float Gs[40][40], Bs[40][40];
    __shared__ float P[8][20][24];
    __shared__ float2 stats[8];
    __shared__ float rs[16][4], rq[16][4];
    const int tile = blockIdx.x, bg = blockIdx.y;
    const int oj0 = (tile & 3) * 16, oi0 = (tile >> 2) * 16;
    const int tid = threadIdx.x, wid = tid >> 5, lid = tid & 31;

    if (wid < 8) {
        int s = bg * 8 + wid;
        float2 a = __ldg(&part1[s * 64 + lid]);
        float2 b = __ldg(&part1[s * 64 + 32 + lid]);
        float sum = a.x + b.x, ssq = a.y + b.y;
#pragma unroll
        for (int o = 16; o; o >>= 1) {
            sum += __shfl_down_sync(0xFFFFFFFFu, sum, o);
            ssq += __shfl_down_sync(0xFFFFFFFFu, ssq, o);
        }
        if (lid == 0) {
            float mu = sum * (1.0f / 16384.0f);
            float var = ssq * (1.0f / 16384.0f) - mu * mu;
            stats[wid] = make_float2(mu, rsqrtf(var + 1e-5f));
        }
    }
    for (int e = tid; e < 800; e += 512) {
        int arr = e / 400;
        int rem = e - arr * 400;
        int q = rem / 10, k = rem - q * 10;
        int gi = 2 * oi0 - 4 + q;
        int c = 2 * oj0 - 4 + 4 * k;
        float4 v = make_float4(0.f, 0.f, 0.f, 0.f);
        if ((unsigned)gi < 128u && (unsigned)c <= 124u)
            v = *(const float4*)((arr ? be1 : g1) + gi * 128 + c);
        if (arr) *(float4*)(&Bs[q][4 * k]) = v;
        else     *(float4*)(&Gs[q][4 * k]) = v;
    }
    __syncthreads();

    for (int e = tid; e < 1600; e += 512) {
        int sIdx = e / 200;
        int rem = e - sIdx * 200;
        int pr = rem / 10, g = rem - pr * 10;
        int pi = oi0 - 2 + pr;
        int pjA = oj0 - 2 + 2 * g;
        float pv0 = 0.0f, pv1 = 0.0f;
        if ((unsigned)pi < 64u && (unsigned)pjA < 63u) {
            float mu = stats[sIdx].x, rstd = stats[sIdx].y;
            int r0 = 2 * pi, c0 = 2 * pjA;
            const float* base = c1 + (bg * 8 + sIdx) * 16384;
            float4 x0 = *(const float4*)(base + r0 * 128 + c0);
            float4 x1 = *(const float4*)(base + (r0 + 1) * 128 + c0);
            int qr = 2 * pr;
            const float* G0 = &Gs[qr][4 * g];
            const float* G1 = &Gs[qr + 1][4 * g];
            const float* B0 = &Bs[qr][4 * g];
            const float* B1 = &Bs[qr + 1][4 * g];
            float n00 = (x0.x - mu) * rstd * G0[0] + B0[0];
            float n01 = (x0.y - mu) * rstd * G0[1] + B0[1];
            float n10 = (x1.x - mu) * rstd * G1[0] + B1[0];
            float n11 = (x1.y - mu) * rstd * G1[1] + B1[1];
            pv0 = fmaxf(fmaxf(n00, n01), fmaxf(n10, n11));
            float m02 = (x0.z - mu) * rstd * G0[2] + B0[2];
            float m03 = (x0.w - mu) * rstd * G0[3] + B0[3];
            float m12 = (x1.z - mu) * rstd * G1[2] + B1[2];
            float m13 = (x1.w - mu) * rstd * G1[3] + B1[3];
            pv1 = fmaxf(fmaxf(m02, m03), fmaxf(m12, m13));
        }
        P[sIdx][pr][2 * g] = pv0;
        P[sIdx][pr][2 * g + 1] = pv1;
    }
    __syncthreads();

    const int pq = tid & 255, sh = tid >> 8;      // position, sample-half
    const int ti = pq >> 4, tj = pq & 15;
    const int p = (oi0 + ti) * 64 + (oj0 + tj);
    const int s0 = sh * 4;
    float4 wq[7];
    const float4* wvp = (const float4*)(wp + OFF_W2);
#pragma unroll
    for (int t = 0; t < 7; ++t) wq[t] = __ldg(wvp + t * 4096 + p);
    const float* wf = (const float*)wq;
    const float bias = __ldg(b2 + p);

    float outv[4];
#pragma unroll
    for (int s = 0; s < 4; ++s) {
        float acc = bias;
#pragma unroll
        for (int u = 0; u < 5; ++u)
#pragma unroll
            for (int v = 0; v < 5; ++v)
                acc = fmaf(P[s0 + s][ti + u][tj + v], wf[u * 5 + v], acc);
        outv[s] = fmaxf(acc, 0.0f);
        out2[(bg * 8 + s0 + s) * 4096 + p] = outv[s];
    }
#pragma unroll
    for (int s = 0; s < 4; ++s) {
        float v = outv[s], q = v * v;
#pragma unroll
        for (int o = 16; o; o >>= 1) {
            v += __shfl_down_sync(0xFFFFFFFFu, v, o);
            q += __shfl_down_sync(0xFFFFFFFFu, q, o);
        }
        if (lid == 0) { rs[wid][s] = v; rq[wid][s] = q; }
    }
    __syncthreads();
    if (tid < 8) {
        int base = (tid < 4) ? 0 : 8;
        int col = tid & 3;
        float s_ = 0.0f, q_ = 0.0f;
#pragma unroll
        for (int w = 0; w < 8; ++w) { s_ += rs[base + w][col]; q_ += rq[base + w][col]; }
        part2[(bg * 8 + tid) * 16 + tile] = make_float2(s_, q_);
    }
}

// ---------------------------------------------------------------------------
// conv3k: LN2(+g2,be2) on the fly, conv3 (64x64, K=5) batch-amortized.
// Grid (16,8), 512 threads: (256 positions) x (2 sample-halves).
// ---------------------------------------------------------------------------
__global__ void __launch_bounds__(512) conv3k_kernel(const float* __restrict__ in2,
                                                     const float2* __restrict__ part2,
                                                     const float* __restrict__ g2,
                                                     const float* __restrict__ be2,
                                                     const float* __restrict__ wp,
                                                     const float* __restrict__ b3,
                                                     float* __restrict__ out3,
                                                     float2* __restrict__ part3) {
    __shared__ float N[8][20][24];
    __shared__ float Gs2[20][24], Bs2[20][24];
    __shared__ float2 stats[8];
    __shared__ float rs[16][4], rq[16][4];
    const int tile = blockIdx.x, bg = blockIdx.y;
    const int oj0 = (tile & 3) * 16, oi0 = (tile >> 2) * 16;
    const int tid = threadIdx.x, wid = tid >> 5, lid = tid & 31;

    if (wid < 8) {
        int s = bg * 8 + wid;
        float2 a = (lid < 16) ? __ldg(&part2[s * 16 + lid]) : make_float2(0.f, 0.f);
        float sum = a.x, ssq = a.y;
#pragma unroll
        for (int o = 16; o; o >>= 1) {
            sum += __shfl_down_sync(0xFFFFFFFFu, sum, o);
            ssq += __shfl_down_sync(0xFFFFFFFFu, ssq, o);
        }
        if (lid == 0) {
            float mu = sum * (1.0f / 4096.0f);
            float var = ssq * (1.0f / 4096.0f) - mu * mu;
            stats[wid] = make_float2(mu, rsqrtf(var + 1e-5f));
        }
    }
    for (int e = tid; e < 240; e += 512) {
        int arr = e / 120;
        int rem = e - arr * 120;
        int q = rem / 6, k = rem - q * 6;
        int ri = oi0 - 2 + q;
        int c = oj0 - 4 + 4 * k;
        float4 v = make_float4(0.f, 0.f, 0.f, 0.f);
        if ((unsigned)ri < 64u && (unsigned)c <= 60u)
            v = *(const float4*)((arr ? be2 : g2) + ri * 64 + c);
        if (arr) *(float4*)(&Bs2[q][4 * k]) = v;
        else     *(float4*)(&Gs2[q][4 * k]) = v;
    }
    __syncthreads();

    for (int e = tid; e < 960; e += 512) {
        int sIdx = e / 120;
        int rem = e - sIdx * 120;
        int q = rem / 6, k = rem - q * 6;
        int ri = oi0 - 2 + q;
        int c = oj0 - 4 + 4 * k;
        float4 nv = make_float4(0.f, 0.f, 0.f, 0.f);
        if ((unsigned)ri < 64u && (unsigned)c <= 60u) {
            float mu = stats[sIdx].x, rstd = stats[sIdx].y;
            float4 xv = *(const float4*)(in2 + (bg * 8 + sIdx) * 4096 + ri * 64 + c);
            const float* G = &Gs2[q][4 * k];
            const float* B = &Bs2[q][4 * k];
            nv.x = (xv.x - mu) * rstd * G[0] + B[0];
            nv.y = (xv.y - mu) * rstd * G[1] + B[1];
            nv.z = (xv.z - mu) * rstd * G[2] + B[2];
            nv.w = (xv.w - mu) * rstd * G[3] + B[3];
        }
        *(float4*)(&N[sIdx][q][4 * k]) = nv;
    }
    __syncthreads();

    const int pq = tid & 255, sh = tid >> 8;
    const int ti = pq >> 4, tj = pq & 15;
    const int p = (oi0 + ti) * 64 + (oj0 + tj);
    const int s0 = sh * 4;
    float4 wq[7];
    const float4* wvp = (const float4*)(wp + OFF_W3);
#pragma unroll
    for (int t = 0; t < 7; ++t) wq[t] = __ldg(wvp + t * 4096 + p);
    const float* wf = (const float*)wq;
    const float bias = __ldg(b3 + p);

    float outv[4];
#pragma unroll
    for (int s = 0; s < 4; ++s) {
        float acc = bias;
#pragma unroll
        for (int u = 0; u < 5; ++u)
#pragma unroll
            for (int v = 0; v < 5; ++v)
                acc = fmaf(N[s0 + s][ti + u][tj + v + 2], wf[u * 5 + v], acc);
        outv[s] = fmaxf(acc, 0.0f);
        out3[(bg * 8 + s0 + s) * 4096 + p] = outv[s];
    }
#pragma unroll
    for (int s = 0; s < 4; ++s) {
        float v = outv[s], q = v * v;
#pragma unroll
        for (int o = 16; o; o >>= 1) {
            v += __shfl_down_sync(0xFFFFFFFFu, v, o);
            q += __shfl_down_sync(0xFFFFFFFFu, q, o);
        }
        if (lid == 0) { rs[wid][s] = v; rq[wid][s] = q; }
    }
    __syncthreads();
    if (tid < 8) {
        int base = (tid < 4) ? 0 : 8;
        int col = tid & 3;
        float s_ = 0.0f, q_ = 0.0f;
#pragma unroll
        for (int w = 0; w < 8; ++w) { s_ += rs[base + w][col]; q_ += rq[base + w][col]; }
        part3[(bg * 8 + tid) * 16 + tile] = make_float2(s_, q_);
    }
}

// ---------------------------------------------------------------------------
__device__ __forceinline__ float2 bstats(float s, float ss) {
    __shared__ float r0[32], r1[32];
    int tid = threadIdx.x, wid = tid >> 5, lid = tid & 31;
#pragma unroll
    for (int o = 16; o; o >>= 1) {
        s += __shfl_down_sync(0xFFFFFFFFu, s, o);
        ss += __shfl_down_sync(0xFFFFFFFFu, ss, o);
    }
    if (lid == 0) { r0[wid] = s; r1[wid] = ss; }
    __syncthreads();
    if (wid == 0) {
        s = r0[lid];
        ss = r1[lid];
#pragma unroll
        for (int o = 16; o; o >>= 1) {
            s += __shfl_down_sync(0xFFFFFFFFu, s, o);
            ss += __shfl_down_sync(0xFFFFFFFFu, ss, o);
        }
        if (lid == 0) { r0[0] = s; r1[0] = ss; }
    }
    __syncthreads();
    float2 res = make_float2(r0[0], r1[0]);
    __syncthreads();
    return res;
}

// ---------------------------------------------------------------------------
// tail: LN3+pool -> conv4 -> LN4 -> conv5 -> LN5+pool -> conv6 -> LN6 -> h.
// Block per sample (grid=64, 1024 threads).
// ---------------------------------------------------------------------------
#define MT 1024
__global__ void __launch_bounds__(MT) tail_kernel(
    const float* __restrict__ in3, const float2* __restrict__ part3,
    const float* __restrict__ g3, const float* __restrict__ be3,
    const float* __restrict__ wp,
    const float* __restrict__ b4, const float* __restrict__ g4, const float* __restrict__ be4,
    const float* __restrict__ b5, const float* __restrict__ g5, const float* __restrict__ be5,
    const float* __restrict__ b6, const float* __restrict__ g6, const float* __restrict__ be6,
    float* __restrict__ hout) {
    __shared__ float SA[1156], SB[1156];
    __shared__ float2 st3;
    const int tid = threadIdx.x;
    const int b = blockIdx.x;

    for (int e = tid; e < 2312; e += MT) (e < 1156 ? SA : SB - 1156)[e] = 0.0f;
    if (tid < 32) {
        float2 a = (tid < 16) ? __ldg(&part3[b * 16 + tid]) : make_float2(0.f, 0.f);
        float sum = a.x, ssq = a.y;
#pragma unroll
        for (int o = 16; o; o >>= 1) {
            sum += __shfl_down_sync(0xFFFFFFFFu, sum, o);
            ssq += __shfl_down_sync(0xFFFFFFFFu, ssq, o);
        }
        if (tid == 0) {
            float mu = sum * (1.0f / 4096.0f);
            float var = ssq * (1.0f / 4096.0f) - mu * mu;
            st3 = make_float2(mu, rsqrtf(var + 1e-5f));
        }
    }
    __syncthreads();

    {
        float mu = st3.x, rstd = st3.y;
        const float* base = in3 + b * 4096;
        for (int e = tid; e < 512; e += MT) {
            int pr = e >> 4, g = e & 15;
            int r0 = 2 * pr, c = 4 * g;
            float4 x0 = *(const float4*)(base + r0 * 64 + c);
            float4 x1 = *(const float4*)(base + (r0 + 1) * 64 + c);
            float4 G0 = *(const float4*)(g3 + r0 * 64 + c);
            float4 G1 = *(const float4*)(g3 + (r0 + 1) * 64 + c);
            float4 B0 = *(const float4*)(be3 + r0 * 64 + c);
            float4 B1 = *(const float4*)(be3 + (r0 + 1) * 64 + c);
            float n00 = (x0.x - mu) * rstd * G0.x + B0.x;
            float n01 = (x0.y - mu) * rstd * G0.y + B0.y;
            float n10 = (x1.x - mu) * rstd * G1.x + B1.x;
            float n11 = (x1.y - mu) * rstd * G1.y + B1.y;
            SB[(pr + 1) * 34 + 2 * g + 1] = fmaxf(fmaxf(n00, n01), fmaxf(n10, n11));
            float m02 = (x0.z - mu) * rstd * G0.z + B0.z;
            float m03 = (x0.w - mu) * rstd * G0.w + B0.w;
            float m12 = (x1.z - mu) * rstd * G1.z + B1.z;
            float m13 = (x1.w - mu) * rstd * G1.w + B1.w;
            SB[(pr + 1) * 34 + 2 * g + 2] = fmaxf(fmaxf(m02, m03), fmaxf(m12, m13));
        }
    }
    __syncthreads();

    // conv4
    float s = 0.0f, ss = 0.0f;
    for (int e = tid; e < 1156; e += MT) {
        int i34 = e / 34, j34 = e - i34 * 34;
        if (i34 == 0 || i34 == 33 || j34 == 0 || j34 == 33) { SA[e] = 0.0f; continue; }
        int io = i34 - 1, jo = j34 - 1;
        int p = io * 32 + jo;
        float4 wq[3];
        const float4* wv4 = (const float4*)(wp + OFF_W4);
#pragma unroll
        for (int t = 0; t < 3; ++t) wq[t] = __ldg(wv4 + t * 1024 + p);
        const float* wf = (const float*)wq;
        const float* src = SB + io * 34 + jo;
        float acc = __ldg(b4 + p);
#pragma unroll
        for (int u = 0; u < 3; ++u)
#pragma unroll
            for (int v = 0; v < 3; ++v)
                acc = fmaf(src[u * 34 + v], wf[u * 3 + v], acc);
        acc = fmaxf(acc, 0.0f);
        SA[e] = acc;
        s += acc; ss += acc * acc;
    }
    float2 st = bstats(s, ss);
    float mu = st.x * (1.0f / 1024.0f);
    float rstd = rsqrtf(st.y * (1.0f / 1024.0f) - mu * mu + 1e-5f);
    for (int p = tid; p < 1024; p += MT) {
        int idx = ((p >> 5) + 1) * 34 + (p & 31) + 1;
        SA[idx] = (SA[idx] - mu) * rstd * __ldg(g4 + p) + __ldg(be4 + p);
    }
    __syncthreads();

    // conv5
    s = ss = 0.0f;
    for (int p = tid; p < 1024; p += MT) {
        int i = p >> 5, j = p & 31;
        float4 wq[3];
        const float4* wv5 = (const float4*)(wp + OFF_W5);
#pragma unroll
        for (int t = 0; t < 3; ++t) wq[t] = __ldg(wv5 + t * 1024 + p);
        const float* wf = (const float*)wq;
        const float* src = SA + i * 34 + j;
        float acc = __ldg(b5 + p);
#pragma unroll
        for (int u = 0; u < 3; ++u)
#pragma unroll
            for (int v = 0; v < 3; ++v)
                acc = fmaf(src[u * 34 + v], wf[u * 3 + v], acc);
        acc = fmaxf(acc, 0.0f);
        SB[(i + 1) * 34 + j + 1] = acc;
        s += acc; ss += acc * acc;
    }
    st = bstats(s, ss);
    mu = st.x * (1.0f / 1024.0f);
    rstd = rsqrtf(st.y * (1.0f / 1024.0f) - mu * mu + 1e-5f);
    for (int e = tid; e < 324; e += MT) {
        int i18 = e / 18, j18 = e - i18 * 18;
        if (i18 == 0 || i18 == 17 || j18 == 0 || j18 == 17) { SA[e] = 0.0f; continue; }
        int io = i18 - 1, jo = j18 - 1;
        float m = -CUDART_INF_F;
#pragma unroll
        for (int di = 0; di < 2; ++di)
#pragma unroll
            for (int dj = 0; dj < 2; ++dj) {
                int gi = 2 * io + di, gj = 2 * jo + dj;
                int q = gi * 32 + gj;
                float v = (SB[(gi + 1) * 34 + gj + 1] - mu) * rstd * __ldg(g5 + q) + __ldg(be5 + q);
                m = fmaxf(m, v);
            }
        SA[e] = m;
    }
    __syncthreads();

    // conv6
    s = ss = 0.0f;
    for (int p = tid; p < 256; p += MT) {
        int i = p >> 4, j = p & 15;
        float4 wq[3];
        const float4* wv6 = (const float4*)(wp + OFF_W6);
#pragma unroll
        for (int t = 0; t < 3; ++t) wq[t] = __ldg(wv6 + t * 256 + p);
        const float* wf = (const float*)wq;
        const float* src = SA + i * 18 + j;
        float acc = __ldg(b6 + p);
#pragma unroll
        for (int u = 0; u < 3; ++u)
#pragma unroll
            for (int v = 0; v < 3; ++v)
                acc = fmaf(src[u * 18 + v], wf[u * 3 + v], acc);
        acc = fmaxf(acc, 0.0f);
        SB[p] = acc;
        s += acc; ss += acc * acc;
    }
    st = bstats(s, ss);
    mu = st.x * (1.0f / 256.0f);
    rstd = rsqrtf(st.y * (1.0f / 256.0f) - mu * mu + 1e-5f);
    for (int p = tid; p < 256; p += MT)
        hout[b * 256 + p] = (SB[p] - mu) * rstd * __ldg(g6 + p) + __ldg(be6 + p);
}

// ---------------------------------------------------------------------------
// FC: grid (32 col-tiles, 16 row-groups of 4 rows), 256 threads.
// ---------------------------------------------------------------------------
__global__ void __launch_bounds__(256) fc_kernel(const float* __restrict__ h,
                                                 const float* __restrict__ fcw,
                                                 const float* __restrict__ fcb,
                                                 float* __restrict__ logits) {
    __shared__ float hs[4 * 256];
    const int ct = blockIdx.x, rg = blockIdx.y;
    const int tid = threadIdx.x, wid = tid >> 5, lid = tid & 31;

    for (int e = tid; e < 1024; e += 256) hs[e] = h[rg * 1024 + e];
    __syncthreads();

    float hr[4][8];
#pragma unroll
    for (int r = 0; r < 4; ++r)
#pragma unroll
        for (int c = 0; c < 8; ++c) hr[r][c] = hs[r * 256 + lid * 8 + c];

    const int obase = ct * 32 + wid * 4;
#pragma unroll
    for (int t = 0; t < 4; ++t) {
        int o = obase + t;
        const float4* wr = (const float4*)(fcw + o * 256 + lid * 8);
        float4 wa = __ldg(wr), wb = __ldg(wr + 1);
        float a[4];
#pragma unroll
        for (int r = 0; r < 4; ++r) {
            a[r] = hr[r][0] * wa.x + hr[r][1] * wa.y + hr[r][2] * wa.z + hr[r][3] * wa.w
                 + hr[r][4] * wb.x + hr[r][5] * wb.y + hr[r][6] * wb.z + hr[r][7] * wb.w;
        }
#pragma unroll
        for (int r = 0; r < 4; ++r)
#pragma unroll
            for (int off = 16; off; off >>= 1) a[r] += __shfl_down_sync(0xFFFFFFFFu, a[r], off);
        if (lid == 0) {
            float bo = __ldg(fcb + o);
#pragma unroll
            for (int r = 0; r < 4; ++r) logits[(rg * 4 + r) * 1024 + o] = a[r] + bo;
        }
    }
}

// ---------------------------------------------------------------------------
// Softmax: grid=64, 512 threads, 2 elements per thread.
// ---------------------------------------------------------------------------
__global__ void __launch_bounds__(512) softmax_kernel(const float* __restrict__ logits,
                                                      float* __restrict__ out) {
    __shared__ float red[16];
    const int b = blockIdx.x, tid = threadIdx.x, wid = tid >> 5, lid = tid & 31;
    const float* row = logits + b * 1024;

    float v0 = row[tid], v1 = row[512 + tid];
    float mx = fmaxf(v0, v1);
#pragma unroll
    for (int o = 16; o; o >>= 1) mx = fmaxf(mx, __shfl_xor_sync(0xFFFFFFFFu, mx, o));
    if (lid == 0) red[wid] = mx;
    __syncthreads();
    mx = red[0];
#pragma unroll
    for (int w = 1; w < 16; ++w) mx = fmaxf(mx, red[w]);
    __syncthreads();

    float e0 = __expf(v0 - mx), e1 = __expf(v1 - mx);
    float ps = e0 + e1;
#pragma unroll
    for (int o = 16; o; o >>= 1) ps += __shfl_xor_sync(0xFFFFFFFFu, ps, o);
    if (lid == 0) red[wid] = ps;
    __syncthreads();
    float tot = 0.0f;
#pragma unroll
    for (int w = 0; w < 16; ++w) tot += red[w];
    float inv = 1.0f / tot;
    out[b * 1024 + tid] = e0 * inv;
    out[b * 1024 + 512 + tid] = e1 * inv;
}

// ---------------------------------------------------------------------------
extern "C" void kernel_launch(void* const* d_in, const int* in_sizes, int n_in,
                              void* d_out, int out_size) {
    (void)in_sizes; (void)n_in; (void)out_size;

    const float* x = (const float*)d_in[0];
    const float* w[7];
    const float* bi[7];
    const float* gg[7];
    const float* bb[7];
    for (int L = 1; L <= 6; ++L) {
        w[L]  = (const float*)d_in[1 + 4 * (L - 1) + 0];
        bi[L] = (const float*)d_in[1 + 4 * (L - 1) + 1];
        gg[L] = (const float*)d_in[1 + 4 * (L - 1) + 2];
        bb[L] = (const float*)d_in[1 + 4 * (L - 1) + 3];
    }
    const float* fcw = (const float*)d_in[25];
    const float* fcb = (const float*)d_in[26];
    float* out = (float*)d_out;

    float *c1, *o2, *o3, *h, *lg, *wp;
    float2 *p1, *p2, *p3;
    cudaGetSymbolAddress((void**)&c1, g_conv1);
    cudaGetSymbolAddress((void**)&o2, g_out2);
    cudaGetSymbolAddress((void**)&o3, g_out3);
    cudaGetSymbolAddress((void**)&h, g_h);
    cudaGetSymbolAddress((void**)&lg, g_logits);
    cudaGetSymbolAddress((void**)&wp, g_wpack);
    cudaGetSymbolAddress((void**)&p1, g_part1);
    cudaGetSymbolAddress((void**)&p2, g_part2);
    cudaGetSymbolAddress((void**)&p3, g_part3);

    repack_kernel<<<256, 256>>>(w[1], w[2], w[3], w[4], w[5], w[6], wp);
    conv1_kernel<<<dim3(64, 8), 256>>>(x, wp, bi[1], c1, p1);
    conv2k_kernel<<<dim3(16, 8), 512>>>(c1, p1, gg[1], bb[1], wp, bi[2], o2, p2);
    conv3k_kernel<<<dim3(16, 8), 512>>>(o2, p2, gg[2], bb[2], wp, bi[3], o3, p3);
    tail_kernel<<<64, MT>>>(o3, p3, gg[3], bb[3], wp,
                            bi[4], gg[4], bb[4],
                            bi[5], gg[5], bb[5],
                            bi[6], gg[6], bb[6],
                            h);
    fc_kernel<<<dim3(32, 16), 256>>>(h, fcw, fcb, lg);
    softmax_kernel<<<64, 512>>>(lg, out);
}

// round 12
// speedup vs baseline: 2.6057x; 1.0698x over previous
#include <cuda_runtime.h>
#include <math_constants.h>

#define BATCH 64

// scratch
__device__ float g_conv1[BATCH * 16384];
__device__ float g_out2[BATCH * 4096];
__device__ float g_out3[BATCH * 4096];
__device__ float g_h[BATCH * 256];
__device__ float g_logits[BATCH * 1024];
__device__ float g_wpack[1141760];
__device__ float2 g_part1[BATCH * 64];
__device__ float2 g_part2[BATCH * 16];
__device__ float2 g_part3[BATCH * 16];

// packed-weight offsets (floats). Layout: [k-group][pos][4] so adjacent
// positions are 16B apart -> warp LDG.128 touches 4 lines, not 32.
#define OFF_W1 0          // 13 groups x 16384 x 4 = 851968
#define OFF_W2 851968     // 7 x 4096 x 4 = 114688
#define OFF_W3 966656     // 7 x 4096 x 4 = 114688
#define OFF_W4 1081344    // 3 x 1024 x 4 = 12288
#define OFF_W5 1093632    // 3 x 1024 x 4 = 12288
#define OFF_W6 1105920    // 3 x 256 x 4 = 3072

// ---------------------------------------------------------------------------
__global__ void repack_kernel(const float* __restrict__ w1, const float* __restrict__ w2,
                              const float* __restrict__ w3, const float* __restrict__ w4,
                              const float* __restrict__ w5, const float* __restrict__ w6,
                              float* __restrict__ wp) {
    int tid = blockIdx.x * blockDim.x + threadIdx.x;
    int nt = gridDim.x * blockDim.x;
    for (int i = tid; i < 16384 * 49; i += nt) {
        int p = i / 49, k = i - p * 49;
        wp[OFF_W1 + ((k >> 2) * 16384 + p) * 4 + (k & 3)] = w1[i];
    }
    for (int i = tid; i < 4096 * 25; i += nt) {
        int p = i / 25, k = i - p * 25;
        wp[OFF_W2 + ((k >> 2) * 4096 + p) * 4 + (k & 3)] = w2[i];
    }
    for (int i = tid; i < 4096 * 25; i += nt) {
        int p = i / 25, k = i - p * 25;
        wp[OFF_W3 + ((k >> 2) * 4096 + p) * 4 + (k & 3)] = w3[i];
    }
    for (int i = tid; i < 1024 * 9; i += nt) {
        int p = i / 9, k = i - p * 9;
        wp[OFF_W4 + ((k >> 2) * 1024 + p) * 4 + (k & 3)] = w4[i];
    }
    for (int i = tid; i < 1024 * 9; i += nt) {
        int p = i / 9, k = i - p * 9;
        wp[OFF_W5 + ((k >> 2) * 1024 + p) * 4 + (k & 3)] = w5[i];
    }
    for (int i = tid; i < 256 * 9; i += nt) {
        int p = i / 9, k = i - p * 9;
        wp[OFF_W6 + ((k >> 2) * 256 + p) * 4 + (k & 3)] = w6[i];
    }
}

// ---------------------------------------------------------------------------
// Conv1: 128x128, K=7, pad=3, + ReLU. Block = 8x32 tile x 8-batch group.
// Grid (64,8), 256 threads.
// ---------------------------------------------------------------------------
__global__ void __launch_bounds__(256) conv1_kernel(const float* __restrict__ x,
                                                    const float* __restrict__ wp,
                                                    const float* __restrict__ b1,
                                                    float* __restrict__ out,
                                                    float2* __restrict__ part1) {
    __shared__ float sm[8][14][40];
    __shared__ float rs[8][8], rq[8][8];
    const int tile = blockIdx.x;
    const int bg = blockIdx.y;
    const int tx = tile & 3, ty = tile >> 2;
    const int tj0 = tx * 32, ti0 = ty * 8;
    const int tid = threadIdx.x;

    for (int e = tid; e < 1120; e += 256) {
        int bb = e / 140;
        int rem = e - bb * 140;
        int r = rem / 10, k = rem - r * 10;
        int gi = ti0 - 3 + r;
        int c = tj0 - 4 + 4 * k;
        float4 v = make_float4(0.f, 0.f, 0.f, 0.f);
        if ((unsigned)gi < 128u && (unsigned)c <= 124u)
            v = *(const float4*)(x + (bg * 8 + bb) * 16384 + gi * 128 + c);
        *(float4*)(&sm[bb][r][4 * k]) = v;
    }

    const int ti = tid >> 5, tj = tid & 31;
    const int p = (ti0 + ti) * 128 + (tj0 + tj);
    float4 wreg[13];
    const float4* wv = (const float4*)(wp + OFF_W1);
#pragma unroll
    for (int t = 0; t < 13; ++t) wreg[t] = __ldg(wv + t * 16384 + p);
    const float* wf = (const float*)wreg;
    const float bias = __ldg(b1 + p);
    __syncthreads();

    float r8[8];
#pragma unroll
    for (int bb = 0; bb < 8; bb += 4) {
        float a0 = bias, a1 = bias, a2 = bias, a3 = bias;
#pragma unroll
        for (int u = 0; u < 7; ++u)
#pragma unroll
            for (int v = 0; v < 7; ++v) {
                float wvv = wf[u * 7 + v];
                a0 = fmaf(sm[bb + 0][ti + u][tj + v + 1], wvv, a0);
                a1 = fmaf(sm[bb + 1][ti + u][tj + v + 1], wvv, a1);
                a2 = fmaf(sm[bb + 2][ti + u][tj + v + 1], wvv, a2);
                a3 = fmaf(sm[bb + 3][ti + u][tj + v + 1], wvv, a3);
            }
        r8[bb + 0] = fmaxf(a0, 0.0f);
        r8[bb + 1] = fmaxf(a1, 0.0f);
        r8[bb + 2] = fmaxf(a2, 0.0f);
        r8[bb + 3] = fmaxf(a3, 0.0f);
    }
#pragma unroll
    for (int bb = 0; bb < 8; ++bb)
        out[(bg * 8 + bb) * 16384 + p] = r8[bb];

    const int wid = tid >> 5, lid = tid & 31;
#pragma unroll
    for (int s = 0; s < 8; ++s) {
        float v = r8[s], q = v * v;
#pragma unroll
        for (int o = 16; o; o >>= 1) {
            v += __shfl_down_sync(0xFFFFFFFFu, v, o);
            q += __shfl_down_sync(0xFFFFFFFFu, q, o);
        }
        if (lid == 0) { rs[wid][s] = v; rq[wid][s] = q; }
    }
    __syncthreads();
    if (tid < 8) {
        float s_ = 0.0f, q_ = 0.0f;
#pragma unroll
        for (int w = 0; w < 8; ++w) { s_ += rs[w][tid]; q_ += rq[w][tid]; }
        part1[(bg * 8 + tid) * 64 + tile] = make_float2(s_, q_);
    }
}

// ---------------------------------------------------------------------------
// conv2k: LN1(+g1,be1) + 2x2 pool on the fly, then conv2 (64x64, K=5)
// batch-amortized. Grid (16 tiles of 16x16, 16 groups of 4 samples),
// 256 threads: thread = 1 position x 4 samples. 2+ blocks/SM for
// phase-interleaved latency hiding.
// ---------------------------------------------------------------------------
__global__ void __launch_bounds__(256) conv2k_kernel(const float* __restrict__ c1,
                                                     const float2* __restrict__ part1,
                                                     const float* __restrict__ g1,
                                                     const float* __restrict__ be1,
                                                     const float* __restrict__ wp,
                                                     const float* __restrict__ b2,
                                                     float* __restrict__ out2,
                                                     float2* __restrict__ part2) {
    __shared__ float Gs[40][40], Bs[40][40];
    __shared__ float P[4][20][24];
    __shared__ float2 stats[4];
    __shared__ float rs[8][4], rq[8][4];
    const int tile = blockIdx.x, bg = blockIdx.y;   // bg: 16 groups of 4
    const int oj0 = (tile & 3) * 16, oi0 = (tile >> 2) * 16;
    const int tid = threadIdx.x, wid = tid >> 5, lid = tid & 31;

    // LN1 stats: warps 0-3 reduce sample bg*4+wid over 64 tile-partials
    if (wid < 4) {
        int s = bg * 4 + wid;
        float2 a = __ldg(&part1[s * 64 + lid]);
        float2 b = __ldg(&part1[s * 64 + 32 + lid]);
        float sum = a.x + b.x, ssq = a.y + b.y;
#pragma unroll
        for (int o = 16; o; o >>= 1) {
            sum += __shfl_down_sync(0xFFFFFFFFu, sum, o);
            ssq += __shfl_down_sync(0xFFFFFFFFu, ssq, o);
        }
        if (lid == 0) {
            float mu = sum * (1.0f / 16384.0f);
            float var = ssq * (1.0f / 16384.0f) - mu * mu;
            stats[wid] = make_float2(mu, rsqrtf(var + 1e-5f));
        }
    }
    for (int e = tid; e < 800; e += 256) {
        int arr = e / 400;
        int rem = e - arr * 400;
        int q = rem / 10, k = rem - q * 10;
        int gi = 2 * oi0 - 4 + q;
        int c = 2 * oj0 - 4 + 4 * k;
        float4 v = make_float4(0.f, 0.f, 0.f, 0.f);
        if ((unsigned)gi < 128u && (unsigned)c <= 124u)
            v = *(const float4*)((arr ? be1 : g1) + gi * 128 + c);
        if (arr) *(float4*)(&Bs[q][4 * k]) = v;
        else     *(float4*)(&Gs[q][4 * k]) = v;
    }
    __syncthreads();

    // build pooled-normalized P[4][20][20] (cols padded to 24)
    for (int e = tid; e < 800; e += 256) {
        int sIdx = e / 200;
        int rem = e - sIdx * 200;
        int pr = rem / 10, g = rem - pr * 10;
        int pi = oi0 - 2 + pr;
        int pjA = oj0 - 2 + 2 * g;
        float pv0 = 0.0f, pv1 = 0.0f;
        if ((unsigned)pi < 64u && (unsigned)pjA < 63u) {
            float mu = stats[sIdx].x, rstd = stats[sIdx].y;
            int r0 = 2 * pi, c0 = 2 * pjA;
            const float* base = c1 + (bg * 4 + sIdx) * 16384;
            float4 x0 = *(const float4*)(base + r0 * 128 + c0);
            float4 x1 = *(const float4*)(base + (r0 + 1) * 128 + c0);
            int qr = 2 * pr;
            const float* G0 = &Gs[qr][4 * g];
            const float* G1 = &Gs[qr + 1][4 * g];
            const float* B0 = &Bs[qr][4 * g];
            const float* B1 = &Bs[qr + 1][4 * g];
            float n00 = (x0.x - mu) * rstd * G0[0] + B0[0];
            float n01 = (x0.y - mu) * rstd * G0[1] + B0[1];
            float n10 = (x1.x - mu) * rstd * G1[0] + B1[0];
            float n11 = (x1.y - mu) * rstd * G1[1] + B1[1];
            pv0 = fmaxf(fmaxf(n00, n01), fmaxf(n10, n11));
            float m02 = (x0.z - mu) * rstd * G0[2] + B0[2];
            float m03 = (x0.w - mu) * rstd * G0[3] + B0[3];
            float m12 = (x1.z - mu) * rstd * G1[2] + B1[2];
            float m13 = (x1.w - mu) * rstd * G1[3] + B1[3];
            pv1 = fmaxf(fmaxf(m02, m03), fmaxf(m12, m13));
        }
        P[sIdx][pr][2 * g] = pv0;
        P[sIdx][pr][2 * g + 1] = pv1;
    }
    __syncthreads();

    const int ti = tid >> 4, tj = tid & 15;
    const int p = (oi0 + ti) * 64 + (oj0 + tj);
    float4 wq[7];
    const float4* wvp = (const float4*)(wp + OFF_W2);
#pragma unroll
    for (int t = 0; t < 7; ++t) wq[t] = __ldg(wvp + t * 4096 + p);
    const float* wf = (const float*)wq;
    const float bias = __ldg(b2 + p);

    float outv[4];
#pragma unroll
    for (int s = 0; s < 4; ++s) {
        float acc = bias;
#pragma unroll
        for (int u = 0; u < 5; ++u)
#pragma unroll
            for (int v = 0; v < 5; ++v)
                acc = fmaf(P[s][ti + u][tj + v], wf[u * 5 + v], acc);
        outv[s] = fmaxf(acc, 0.0f);
        out2[(bg * 4 + s) * 4096 + p] = outv[s];
    }
#pragma unroll
    for (int s = 0; s < 4; ++s) {
        float v = outv[s], q = v * v;
#pragma unroll
        for (int o = 16; o; o >>= 1) {
            v += __shfl_down_sync(0xFFFFFFFFu, v, o);
            q += __shfl_down_sync(0xFFFFFFFFu, q, o);
        }
        if (lid == 0) { rs[wid][s] = v; rq[wid][s] = q; }
    }
    __syncthreads();
    if (tid < 4) {
        float s_ = 0.0f, q_ = 0.0f;
#pragma unroll
        for (int w = 0; w < 8; ++w) { s_ += rs[w][tid]; q_ += rq[w][tid]; }
        part2[(bg * 4 + tid) * 16 + tile] = make_float2(s_, q_);
    }
}

// ---------------------------------------------------------------------------
// conv3k: LN2(+g2,be2) on the fly, conv3 (64x64, K=5) batch-amortized.
// Grid (16, 16 groups of 4), 256 threads: 1 position x 4 samples.
// ---------------------------------------------------------------------------
__global__ void __launch_bounds__(256) conv3k_kernel(const float* __restrict__ in2,
                                                     const float2* __restrict__ part2,
                                                     const float* __restrict__ g2,
                                                     const float* __restrict__ be2,
                                                     const float* __restrict__ wp,
                                                     const float* __restrict__ b3,
                                                     float* __restrict__ out3,
                                                     float2* __restrict__ part3) {
    __shared__ float N[4][20][24];
    __shared__ float Gs2[20][24], Bs2[20][24];
    __shared__ float2 stats[4];
    __shared__ float rs[8][4], rq[8][4];
    const int tile = blockIdx.x, bg = blockIdx.y;
    const int oj0 = (tile & 3) * 16, oi0 = (tile >> 2) * 16;
    const int tid = threadIdx.x, wid = tid >> 5, lid = tid & 31;

    if (wid < 4) {
        int s = bg * 4 + wid;
        float2 a = (lid < 16) ? __ldg(&part2[s * 16 + lid]) : make_float2(0.f, 0.f);
        float sum = a.x, ssq = a.y;
#pragma unroll
        for (int o = 16; o; o >>= 1) {
            sum += __shfl_down_sync(0xFFFFFFFFu, sum, o);
            ssq += __shfl_down_sync(0xFFFFFFFFu, ssq, o);
        }
        if (lid == 0) {
            float mu = sum * (1.0f / 4096.0f);
            float var = ssq * (1.0f / 4096.0f) - mu * mu;
            stats[wid] = make_float2(mu, rsqrtf(var + 1e-5f));
        }
    }
    for (int e = tid; e < 240; e += 256) {
        int arr = e / 120;
        int rem = e - arr * 120;
        int q = rem / 6, k = rem - q * 6;
        int ri = oi0 - 2 + q;
        int c = oj0 - 4 + 4 * k;
        float4 v = make_float4(0.f, 0.f, 0.f, 0.f);
        if ((unsigned)ri < 64u && (unsigned)c <= 60u)
            v = *(const float4*)((arr ? be2 : g2) + ri * 64 + c);
        if (arr) *(float4*)(&Bs2[q][4 * k]) = v;
        else     *(float4*)(&Gs2[q][4 * k]) = v;
    }
    __syncthreads();

    for (int e = tid; e < 480; e += 256) {
        int sIdx = e / 120;
        int rem = e - sIdx * 120;
        int q = rem / 6, k = rem - q * 6;
        int ri = oi0 - 2 + q;
        int c = oj0 - 4 + 4 * k;
        float4 nv = make_float4(0.f, 0.f, 0.f, 0.f);
        if ((unsigned)ri < 64u && (unsigned)c <= 60u) {
            float mu = stats[sIdx].x, rstd = stats[sIdx].y;
            float4 xv = *(const float4*)(in2 + (bg * 4 + sIdx) * 4096 + ri * 64 + c);
            const float* G = &Gs2[q][4 * k];
            const float* B = &Bs2[q][4 * k];
            nv.x = (xv.x - mu) * rstd * G[0] + B[0];
            nv.y = (xv.y - mu) * rstd * G[1] + B[1];
            nv.z = (xv.z - mu) * rstd * G[2] + B[2];
            nv.w = (xv.w - mu) * rstd * G[3] + B[3];
        }
        *(float4*)(&N[sIdx][q][4 * k]) = nv;
    }
    __syncthreads();

    const int ti = tid >> 4, tj = tid & 15;
    const int p = (oi0 + ti) * 64 + (oj0 + tj);
    float4 wq[7];
    const float4* wvp = (const float4*)(wp + OFF_W3);
#pragma unroll
    for (int t = 0; t < 7; ++t) wq[t] = __ldg(wvp + t * 4096 + p);
    const float* wf = (const float*)wq;
    const float bias = __ldg(b3 + p);

    float outv[4];
#pragma unroll
    for (int s = 0; s < 4; ++s) {
        float acc = bias;
#pragma unroll
        for (int u = 0; u < 5; ++u)
#pragma unroll
            for (int v = 0; v < 5; ++v)
                acc = fmaf(N[s][ti + u][tj + v + 2], wf[u * 5 + v], acc);
        outv[s] = fmaxf(acc, 0.0f);
        out3[(bg * 4 + s) * 4096 + p] = outv[s];
    }
#pragma unroll
    for (int s = 0; s < 4; ++s) {
        float v = outv[s], q = v * v;
#pragma unroll
        for (int o = 16; o; o >>= 1) {
            v += __shfl_down_sync(0xFFFFFFFFu, v, o);
            q += __shfl_down_sync(0xFFFFFFFFu, q, o);
        }
        if (lid == 0) { rs[wid][s] = v; rq[wid][s] = q; }
    }
    __syncthreads();
    if (tid < 4) {
        float s_ = 0.0f, q_ = 0.0f;
#pragma unroll
        for (int w = 0; w < 8; ++w) { s_ += rs[w][tid]; q_ += rq[w][tid]; }
        part3[(bg * 4 + tid) * 16 + tile] = make_float2(s_, q_);
    }
}

// ---------------------------------------------------------------------------
__device__ __forceinline__ float2 bstats(float s, float ss) {
    __shared__ float r0[32], r1[32];
    int tid = threadIdx.x, wid = tid >> 5, lid = tid & 31;
#pragma unroll
    for (int o = 16; o; o >>= 1) {
        s += __shfl_down_sync(0xFFFFFFFFu, s, o);
        ss += __shfl_down_sync(0xFFFFFFFFu, ss, o);
    }
    if (lid == 0) { r0[wid] = s; r1[wid] = ss; }
    __syncthreads();
    if (wid == 0) {
        s = r0[lid];
        ss = r1[lid];
#pragma unroll
        for (int o = 16; o; o >>= 1) {
            s += __shfl_down_sync(0xFFFFFFFFu, s, o);
            ss += __shfl_down_sync(0xFFFFFFFFu, ss, o);
        }
        if (lid == 0) { r0[0] = s; r1[0] = ss; }
    }
    __syncthreads();
    float2 res = make_float2(r0[0], r1[0]);
    __syncthreads();
    return res;
}

// ---------------------------------------------------------------------------
// tail: LN3+pool -> conv4 -> LN4 -> conv5 -> LN5+pool -> conv6 -> LN6 -> h.
// Block per sample (grid=64, 1024 threads).
// ---------------------------------------------------------------------------
#define MT 1024
__global__ void __launch_bounds__(MT) tail_kernel(
    const float* __restrict__ in3, const float2* __restrict__ part3,
    const float* __restrict__ g3, const float* __restrict__ be3,
    const float* __restrict__ wp,
    const float* __restrict__ b4, const float* __restrict__ g4, const float* __restrict__ be4,
    const float* __restrict__ b5, const float* __restrict__ g5, const float* __restrict__ be5,
    const float* __restrict__ b6, const float* __restrict__ g6, const float* __restrict__ be6,
    float* __restrict__ hout) {
    __shared__ float SA[1156], SB[1156];
    __shared__ float2 st3;
    const int tid = threadIdx.x;
    const int b = blockIdx.x;

    for (int e = tid; e < 2312; e += MT) (e < 1156 ? SA : SB - 1156)[e] = 0.0f;
    if (tid < 32) {
        float2 a = (tid < 16) ? __ldg(&part3[b * 16 + tid]) : make_float2(0.f, 0.f);
        float sum = a.x, ssq = a.y;
#pragma unroll
        for (int o = 16; o; o >>= 1) {
            sum += __shfl_down_sync(0xFFFFFFFFu, sum, o);
            ssq += __shfl_down_sync(0xFFFFFFFFu, ssq, o);
        }
        if (tid == 0) {
            float mu = sum * (1.0f / 4096.0f);
            float var = ssq * (1.0f / 4096.0f) - mu * mu;
            st3 = make_float2(mu, rsqrtf(var + 1e-5f));
        }
    }
    __syncthreads();

    {
        float mu = st3.x, rstd = st3.y;
        const float* base = in3 + b * 4096;
        for (int e = tid; e < 512; e += MT) {
            int pr = e >> 4, g = e & 15;
            int r0 = 2 * pr, c = 4 * g;
            float4 x0 = *(const float4*)(base + r0 * 64 + c);
            float4 x1 = *(const float4*)(base + (r0 + 1) * 64 + c);
            float4 G0 = *(const float4*)(g3 + r0 * 64 + c);
            float4 G1 = *(const float4*)(g3 + (r0 + 1) * 64 + c);
            float4 B0 = *(const float4*)(be3 + r0 * 64 + c);
            float4 B1 = *(const float4*)(be3 + (r0 + 1) * 64 + c);
            float n00 = (x0.x - mu) * rstd * G0.x + B0.x;
            float n01 = (x0.y - mu) * rstd * G0.y + B0.y;
            float n10 = (x1.x - mu) * rstd * G1.x + B1.x;
            float n11 = (x1.y - mu) * rstd * G1.y + B1.y;
            SB[(pr + 1) * 34 + 2 * g + 1] = fmaxf(fmaxf(n00, n01), fmaxf(n10, n11));
            float m02 = (x0.z - mu) * rstd * G0.z + B0.z;
            float m03 = (x0.w - mu) * rstd * G0.w + B0.w;
            float m12 = (x1.z - mu) * rstd * G1.z + B1.z;
            float m13 = (x1.w - mu) * rstd * G1.w + B1.w;
            SB[(pr + 1) * 34 + 2 * g + 2] = fmaxf(fmaxf(m02, m03), fmaxf(m12, m13));
        }
    }
    __syncthreads();

    // conv4
    float s = 0.0f, ss = 0.0f;
    for (int e = tid; e < 1156; e += MT) {
        int i34 = e / 34, j34 = e - i34 * 34;
        if (i34 == 0 || i34 == 33 || j34 == 0 || j34 == 33) { SA[e] = 0.0f; continue; }
        int io = i34 - 1, jo = j34 - 1;
        int p = io * 32 + jo;
        float4 wq[3];
        const float4* wv4 = (const float4*)(wp + OFF_W4);
#pragma unroll
        for (int t = 0; t < 3; ++t) wq[t] = __ldg(wv4 + t * 1024 + p);
        const float* wf = (const float*)wq;
        const float* src = SB + io * 34 + jo;
        float acc = __ldg(b4 + p);
#pragma unroll
        for (int u = 0; u < 3; ++u)
#pragma unroll
            for (int v = 0; v < 3; ++v)
                acc = fmaf(src[u * 34 + v], wf[u * 3 + v], acc);
        acc = fmaxf(acc, 0.0f);
        SA[e] = acc;
        s += acc; ss += acc * acc;
    }
    float2 st = bstats(s, ss);
    float mu = st.x * (1.0f / 1024.0f);
    float rstd = rsqrtf(st.y * (1.0f / 1024.0f) - mu * mu + 1e-5f);
    for (int p = tid; p < 1024; p += MT) {
        int idx = ((p >> 5) + 1) * 34 + (p & 31) + 1;
        SA[idx] = (SA[idx] - mu) * rstd * __ldg(g4 + p) + __ldg(be4 + p);
    }
    __syncthreads();

    // conv5
    s = ss = 0.0f;
    for (int p = tid; p < 1024; p += MT) {
        int i = p >> 5, j = p & 31;
        float4 wq[3];
        const float4* wv5 = (const float4*)(wp + OFF_W5);
#pragma unroll
        for (int t = 0; t < 3; ++t) wq[t] = __ldg(wv5 + t * 1024 + p);
        const float* wf = (const float*)wq;
        const float* src = SA + i * 34 + j;
        float acc = __ldg(b5 + p);
#pragma unroll
        for (int u = 0; u < 3; ++u)
#pragma unroll
            for (int v = 0; v < 3; ++v)
                acc = fmaf(src[u * 34 + v], wf[u * 3 + v], acc);
        acc = fmaxf(acc, 0.0f);
        SB[(i + 1) * 34 + j + 1] = acc;
        s += acc; ss += acc * acc;
    }
    st = bstats(s, ss);
    mu = st.x * (1.0f / 1024.0f);
    rstd = rsqrtf(st.y * (1.0f / 1024.0f) - mu * mu + 1e-5f);
    for (int e = tid; e < 324; e += MT) {
        int i18 = e / 18, j18 = e - i18 * 18;
        if (i18 == 0 || i18 == 17 || j18 == 0 || j18 == 17) { SA[e] = 0.0f; continue; }
        int io = i18 - 1, jo = j18 - 1;
        float m = -CUDART_INF_F;
#pragma unroll
        for (int di = 0; di < 2; ++di)
#pragma unroll
            for (int dj = 0; dj < 2; ++dj) {
                int gi = 2 * io + di, gj = 2 * jo + dj;
                int q = gi * 32 + gj;
                float v = (SB[(gi + 1) * 34 + gj + 1] - mu) * rstd * __ldg(g5 + q) + __ldg(be5 + q);
                m = fmaxf(m, v);
            }
        SA[e] = m;
    }
    __syncthreads();

    // conv6
    s = ss = 0.0f;
    for (int p = tid; p < 256; p += MT) {
        int i = p >> 4, j = p & 15;
        float4 wq[3];
        const float4* wv6 = (const float4*)(wp + OFF_W6);
#pragma unroll
        for (int t = 0; t < 3; ++t) wq[t] = __ldg(wv6 + t * 256 + p);
        const float* wf = (const float*)wq;
        const float* src = SA + i * 18 + j;
        float acc = __ldg(b6 + p);
#pragma unroll
        for (int u = 0; u < 3; ++u)
#pragma unroll
            for (int v = 0; v < 3; ++v)
                acc = fmaf(src[u * 18 + v], wf[u * 3 + v], acc);
        acc = fmaxf(acc, 0.0f);
        SB[p] = acc;
        s += acc; ss += acc * acc;
    }
    st = bstats(s, ss);
    mu = st.x * (1.0f / 256.0f);
    rstd = rsqrtf(st.y * (1.0f / 256.0f) - mu * mu + 1e-5f);
    for (int p = tid; p < 256; p += MT)
        hout[b * 256 + p] = (SB[p] - mu) * rstd * __ldg(g6 + p) + __ldg(be6 + p);
}

// ---------------------------------------------------------------------------
// FC: grid (32 col-tiles, 16 row-groups of 4 rows), 256 threads.
// ---------------------------------------------------------------------------
__global__ void __launch_bounds__(256) fc_kernel(const float* __restrict__ h,
                                                 const float* __restrict__ fcw,
                                                 const float* __restrict__ fcb,
                                                 float* __restrict__ logits) {
    __shared__ float hs[4 * 256];
    const int ct = blockIdx.x, rg = blockIdx.y;
    const int tid = threadIdx.x, wid = tid >> 5, lid = tid & 31;

    for (int e = tid; e < 1024; e += 256) hs[e] = h[rg * 1024 + e];
    __syncthreads();

    float hr[4][8];
#pragma unroll
    for (int r = 0; r < 4; ++r)
#pragma unroll
        for (int c = 0; c < 8; ++c) hr[r][c] = hs[r * 256 + lid * 8 + c];

    const int obase = ct * 32 + wid * 4;
#pragma unroll
    for (int t = 0; t < 4; ++t) {
        int o = obase + t;
        const float4* wr = (const float4*)(fcw + o * 256 + lid * 8);
        float4 wa = __ldg(wr), wb = __ldg(wr + 1);
        float a[4];
#pragma unroll
        for (int r = 0; r < 4; ++r) {
            a[r] = hr[r][0] * wa.x + hr[r][1] * wa.y + hr[r][2] * wa.z + hr[r][3] * wa.w
                 + hr[r][4] * wb.x + hr[r][5] * wb.y + hr[r][6] * wb.z + hr[r][7] * wb.w;
        }
#pragma unroll
        for (int r = 0; r < 4; ++r)
#pragma unroll
            for (int off = 16; off; off >>= 1) a[r] += __shfl_down_sync(0xFFFFFFFFu, a[r], off);
        if (lid == 0) {
            float bo = __ldg(fcb + o);
#pragma unroll
            for (int r = 0; r < 4; ++r) logits[(rg * 4 + r) * 1024 + o] = a[r] + bo;
        }
    }
}

// ---------------------------------------------------------------------------
// Softmax: grid=64, 512 threads, 2 elements per thread.
// ---------------------------------------------------------------------------
__global__ void __launch_bounds__(512) softmax_kernel(const float* __restrict__ logits,
                                                      float* __restrict__ out) {
    __shared__ float red[16];
    const int b = blockIdx.x, tid = threadIdx.x, wid = tid >> 5, lid = tid & 31;
    const float* row = logits + b * 1024;

    float v0 = row[tid], v1 = row[512 + tid];
    float mx = fmaxf(v0, v1);
#pragma unroll
    for (int o = 16; o; o >>= 1) mx = fmaxf(mx, __shfl_xor_sync(0xFFFFFFFFu, mx, o));
    if (lid == 0) red[wid] = mx;
    __syncthreads();
    mx = red[0];
#pragma unroll
    for (int w = 1; w < 16; ++w) mx = fmaxf(mx, red[w]);
    __syncthreads();

    float e0 = __expf(v0 - mx), e1 = __expf(v1 - mx);
    float ps = e0 + e1;
#pragma unroll
    for (int o = 16; o; o >>= 1) ps += __shfl_xor_sync(0xFFFFFFFFu, ps, o);
    if (lid == 0) red[wid] = ps;
    __syncthreads();
    float tot = 0.0f;
#pragma unroll
    for (int w = 0; w < 16; ++w) tot += red[w];
    float inv = 1.0f / tot;
    out[b * 1024 + tid] = e0 * inv;
    out[b * 1024 + 512 + tid] = e1 * inv;
}

// ---------------------------------------------------------------------------
extern "C" void kernel_launch(void* const* d_in, const int* in_sizes, int n_in,
                              void* d_out, int out_size) {
    (void)in_sizes; (void)n_in; (void)out_size;

    const float* x = (const float*)d_in[0];
    const float* w[7];
    const float* bi[7];
    const float* gg[7];
    const float* bb[7];
    for (int L = 1; L <= 6; ++L) {
        w[L]  = (const float*)d_in[1 + 4 * (L - 1) + 0];
        bi[L] = (const float*)d_in[1 + 4 * (L - 1) + 1];
        gg[L] = (const float*)d_in[1 + 4 * (L - 1) + 2];
        bb[L] = (const float*)d_in[1 + 4 * (L - 1) + 3];
    }
    const float* fcw = (const float*)d_in[25];
    const float* fcb = (const float*)d_in[26];
    float* out = (float*)d_out;

    float *c1, *o2, *o3, *h, *lg, *wp;
    float2 *p1, *p2, *p3;
    cudaGetSymbolAddress((void**)&c1, g_conv1);
    cudaGetSymbolAddress((void**)&o2, g_out2);
    cudaGetSymbolAddress((void**)&o3, g_out3);
    cudaGetSymbolAddress((void**)&h, g_h);
    cudaGetSymbolAddress((void**)&lg, g_logits);
    cudaGetSymbolAddress((void**)&wp, g_wpack);
    cudaGetSymbolAddress((void**)&p1, g_part1);
    cudaGetSymbolAddress((void**)&p2, g_part2);
    cudaGetSymbolAddress((void**)&p3, g_part3);

    repack_kernel<<<256, 256>>>(w[1], w[2], w[3], w[4], w[5], w[6], wp);
    conv1_kernel<<<dim3(64, 8), 256>>>(x, wp, bi[1], c1, p1);
    conv2k_kernel<<<dim3(16, 16), 256>>>(c1, p1, gg[1], bb[1], wp, bi[2], o2, p2);
    conv3k_kernel<<<dim3(16, 16), 256>>>(o2, p2, gg[2], bb[2], wp, bi[3], o3, p3);
    tail_kernel<<<64, MT>>>(o3, p3, gg[3], bb[3], wp,
                            bi[4], gg[4], bb[4],
                            bi[5], gg[5], bb[5],
                            bi[6], gg[6], bb[6],
                            h);
    fc_kernel<<<dim3(32, 16), 256>>>(h, fcw, fcb, lg);
    softmax_kernel<<<64, 512>>>(lg, out);
}